// round 14
// baseline (speedup 1.0000x reference)
#include <cuda_runtime.h>
#include <cuda_bf16.h>
#include <cstdint>
#include <math.h>

#define BB   4
#define NN   4096
#define FIN  512
#define FOUT 256
#define NEG_BIG (-9.0e15f)

// ---------------- scratch (no allocations allowed) ----------------
__device__ float g_as[BB * NN];                   // attn_self   (atomic-accumulated)
__device__ float g_an[BB * NN];                   // attn_neigh
__device__ __nv_bfloat16 g_hth[BB * FOUT * NN];   // h^T hi  [B,256,4096]
__device__ __nv_bfloat16 g_htl[BB * FOUT * NN];   // h^T lo
__device__ __nv_bfloat16 g_wth[FOUT * FIN];       // W^T hi  [256,512]
__device__ __nv_bfloat16 g_wtl[FOUT * FIN];       // W^T lo
__device__ __nv_bfloat16 g_xh [BB * NN * FIN];    // x hi    [B*N,512]
__device__ __nv_bfloat16 g_xl [BB * NN * FIN];    // x lo
__device__ __nv_bfloat16 g_ph [(size_t)BB * NN * NN];  // P hi [B,N,N]
__device__ __nv_bfloat16 g_pl [(size_t)BB * NN * NN];  // P lo

// ================= helpers =================
__device__ __forceinline__ uint32_t smem_u32(const void* p) {
    uint32_t a;
    asm("{ .reg .u64 t; cvta.to.shared.u64 t, %1; cvt.u32.u64 %0, t; }" : "=r"(a) : "l"(p));
    return a;
}
#define SW128(o) ((o) ^ (((o) >> 3) & 0x70))

__device__ __forceinline__ void cp16(uint32_t dst, const void* src) {
    asm volatile("cp.async.cg.shared.global [%0], [%1], 16;\n" :: "r"(dst), "l"(src));
}
__device__ __forceinline__ void ldsm_x4(uint32_t* r, uint32_t addr) {
    asm volatile("ldmatrix.sync.aligned.m8n8.x4.shared.b16 {%0,%1,%2,%3}, [%4];"
        : "=r"(r[0]), "=r"(r[1]), "=r"(r[2]), "=r"(r[3]) : "r"(addr));
}
__device__ __forceinline__ void mma_bf16(float* d, const uint32_t* a, const uint32_t* b) {
    asm volatile("mma.sync.aligned.m16n8k16.row.col.f32.bf16.bf16.f32 "
        "{%0,%1,%2,%3}, {%4,%5,%6,%7}, {%8,%9}, {%0,%1,%2,%3};"
        : "+f"(d[0]), "+f"(d[1]), "+f"(d[2]), "+f"(d[3])
        : "r"(a[0]), "r"(a[1]), "r"(a[2]), "r"(a[3]), "r"(b[0]), "r"(b[1]));
}

// packed hi/lo bf16 split of two floats: hp = bf16x2{lo=x, hi=y}, lp = residuals
__device__ __forceinline__ void split2(float x, float y, uint32_t& hp, uint32_t& lp) {
    asm("cvt.rn.bf16x2.f32 %0, %1, %2;" : "=r"(hp) : "f"(y), "f"(x));
    float lx = x - __uint_as_float(hp << 16);
    float ly = y - __uint_as_float(hp & 0xFFFF0000u);
    asm("cvt.rn.bf16x2.f32 %0, %1, %2;" : "=r"(lp) : "f"(ly), "f"(lx));
}

// ================= generalized mma.sync bf16 hi/lo GEMM (pure async) =======
// C[b][M,256] = A[b][M,Kdim] @ B[b][256,Kdim]^T; A AND B pre-split bf16 hi/lo.
// CTA tile 64(M) x 128(N), K chunk 64; 256 threads, 8 warps 2(M)x4(N),
// warp tile 32x32. 2 smem stages x 48KB -> 2 CTAs/SM co-resident.
// MODE 1: ELU epilogue -> Cg (K4).  MODE 2: transposed hi/lo split of result
// into g_hth/g_htl + attn dot partials into g_as/g_an (K1; Cg unused).
#define KB_CH 64
#define STAGE 49152
#define OAH 0
#define OAL 8192
#define OBH 16384
#define OBL 32768
#define SMP 133   // smem transpose row pitch (floats)
#define NT  256

template<int MODE>
__global__ __launch_bounds__(NT, 2) void mma_gemm(
    const __nv_bfloat16* __restrict__ Ahb, const __nv_bfloat16* __restrict__ Alb,
    const __nv_bfloat16* __restrict__ Bhb, const __nv_bfloat16* __restrict__ Blb,
    float* __restrict__ Cbase, int Kdim, size_t sA, size_t sB, size_t sC,
    const float* __restrict__ att1, const float* __restrict__ att2)
{
    extern __shared__ char dynsmem[];
    const int tid = threadIdx.x;
    const int wid = tid >> 5, lane = tid & 31;
    const int mtile = blockIdx.x, ntile = blockIdx.y, b = blockIdx.z;
    const int rowBase = mtile * 64;
    const int colBase = ntile * 128;
    const int wm = wid >> 2, wn = wid & 3;   // warp tile 32(M) x 32(N)

    uint32_t raw = smem_u32(dynsmem);
    uint32_t sbase = (raw + 1023u) & ~1023u;
    char* dbase = dynsmem + (sbase - raw);

    const __nv_bfloat16* Ahg = Ahb + (size_t)b * sA + (size_t)rowBase * Kdim;
    const __nv_bfloat16* Alg = Alb + (size_t)b * sA + (size_t)rowBase * Kdim;
    const __nv_bfloat16* Bhg = Bhb + (size_t)b * sB + (size_t)colBase * Kdim;
    const __nv_bfloat16* Blg = Blb + (size_t)b * sB + (size_t)colBase * Kdim;
    float* Cg = Cbase + (size_t)b * sC;

    // ldmatrix address components (fixed per thread)
    const uint32_t a_row_l = lane & 15;
    const uint32_t a_k16   = (lane >> 4) * 16;
    const uint32_t a_xor   = (a_row_l & 7) << 4;
    uint32_t a_rowoff[2];
    #pragma unroll
    for (int mf = 0; mf < 2; mf++)
        a_rowoff[mf] = (uint32_t)(wm * 32 + mf * 16 + a_row_l) * 128;

    const uint32_t b_nl  = (lane & 7) + ((lane >> 4) & 1) * 8;
    const uint32_t b_k16 = ((lane >> 3) & 1) * 16;
    const uint32_t b_xor = (b_nl & 7) << 4;
    uint32_t b_rowoff[2];
    #pragma unroll
    for (int np = 0; np < 2; np++)
        b_rowoff[np] = (uint32_t)(wn * 32 + np * 16 + b_nl) * 128;

    float acc[2][4][4] = {};

    // ---- stage-fill: pure cp.async ----
    auto cpStage = [&](uint32_t stb, int kc) {
        #pragma unroll
        for (int l = 0; l < 2; l++) {                 // A: 64 rows x 8 chunks
            int id = tid + l * NT;
            int r = id >> 3, ch = id & 7;
            size_t so = (size_t)r * Kdim + kc + ch * 8;
            uint32_t sw = SW128((uint32_t)(r * 128 + ch * 16));
            cp16(stb + OAH + sw, Ahg + so);
            cp16(stb + OAL + sw, Alg + so);
        }
        #pragma unroll
        for (int l = 0; l < 4; l++) {                 // B: 128 rows x 8 chunks
            int id = tid + l * NT;
            int r = id >> 3, ch = id & 7;
            size_t so = (size_t)r * Kdim + kc + ch * 8;
            uint32_t sw = SW128((uint32_t)(r * 128 + ch * 16));
            cp16(stb + OBH + sw, Bhg + so);
            cp16(stb + OBL + sw, Blg + so);
        }
    };
    auto compute = [&](uint32_t stb) {
        #pragma unroll
        for (int ks = 0; ks < 4; ks++) {
            uint32_t akt = ((uint32_t)(ks * 32) + a_k16) ^ a_xor;
            uint32_t bkt = ((uint32_t)(ks * 32) + b_k16) ^ b_xor;
            uint32_t ah[2][4], al[2][4];
            #pragma unroll
            for (int mf = 0; mf < 2; mf++) {
                ldsm_x4(ah[mf], stb + OAH + a_rowoff[mf] + akt);
                ldsm_x4(al[mf], stb + OAL + a_rowoff[mf] + akt);
            }
            #pragma unroll
            for (int np = 0; np < 2; np++) {
                uint32_t bh[4], bl[4];
                ldsm_x4(bh, stb + OBH + b_rowoff[np] + bkt);
                ldsm_x4(bl, stb + OBL + b_rowoff[np] + bkt);
                // per-accumulator term order ah*bh -> ah*bl -> al*bh (bitwise fixed)
                #pragma unroll
                for (int mf = 0; mf < 2; mf++) mma_bf16(acc[mf][np*2],   ah[mf], &bh[0]);
                #pragma unroll
                for (int mf = 0; mf < 2; mf++) mma_bf16(acc[mf][np*2+1], ah[mf], &bh[2]);
                #pragma unroll
                for (int mf = 0; mf < 2; mf++) mma_bf16(acc[mf][np*2],   ah[mf], &bl[0]);
                #pragma unroll
                for (int mf = 0; mf < 2; mf++) mma_bf16(acc[mf][np*2+1], ah[mf], &bl[2]);
                #pragma unroll
                for (int mf = 0; mf < 2; mf++) mma_bf16(acc[mf][np*2],   al[mf], &bh[0]);
                #pragma unroll
                for (int mf = 0; mf < 2; mf++) mma_bf16(acc[mf][np*2+1], al[mf], &bh[2]);
            }
        }
    };

    // ---- pipeline ----
    cpStage(sbase, 0);
    asm volatile("cp.async.commit_group;" ::: "memory");
    asm volatile("cp.async.wait_group 0;" ::: "memory");
    __syncthreads();

    const int nch = Kdim / KB_CH;
    int buf = 0;
    for (int c = 0; c < nch; c++) {
        int nb = buf ^ 1;
        bool more = (c + 1 < nch);
        if (more) {
            cpStage(sbase + nb * STAGE, (c + 1) * KB_CH);
            asm volatile("cp.async.commit_group;" ::: "memory");
        }
        compute(sbase + buf * STAGE);
        if (more) {
            asm volatile("cp.async.wait_group 0;" ::: "memory");
            __syncthreads();
        }
        buf = nb;
    }

    if (MODE == 1) {
        // ---- ELU + store ----
        #pragma unroll
        for (int mf = 0; mf < 2; mf++) {
            int r0 = rowBase + wm * 32 + mf * 16 + (lane >> 2);
            float* p0 = Cg + (size_t)r0 * FOUT + colBase + wn * 32 + (lane & 3) * 2;
            #pragma unroll
            for (int nf = 0; nf < 4; nf++) {
                float* q = p0 + nf * 8;
                float v0 = acc[mf][nf][0], v1 = acc[mf][nf][1];
                float v2 = acc[mf][nf][2], v3 = acc[mf][nf][3];
                v0 = (v0 > 0.f) ? v0 : expm1f(v0);
                v1 = (v1 > 0.f) ? v1 : expm1f(v1);
                v2 = (v2 > 0.f) ? v2 : expm1f(v2);
                v3 = (v3 > 0.f) ? v3 : expm1f(v3);
                *(float2*)q = make_float2(v0, v1);
                *(float2*)(q + 8 * FOUT) = make_float2(v2, v3);
            }
        }
    } else {
        // ---- attn dot partials from fragments ----
        float a1v[8], a2v[8];
        #pragma unroll
        for (int nf = 0; nf < 4; nf++) {
            int c0 = colBase + wn * 32 + nf * 8 + (lane & 3) * 2;
            a1v[nf*2+0] = __ldg(att1 + c0);  a1v[nf*2+1] = __ldg(att1 + c0 + 1);
            a2v[nf*2+0] = __ldg(att2 + c0);  a2v[nf*2+1] = __ldg(att2 + c0 + 1);
        }
        #pragma unroll
        for (int mf = 0; mf < 2; mf++) {
            float s1a = 0.f, s2a = 0.f, s1b = 0.f, s2b = 0.f;
            #pragma unroll
            for (int nf = 0; nf < 4; nf++) {
                s1a += acc[mf][nf][0] * a1v[nf*2] + acc[mf][nf][1] * a1v[nf*2+1];
                s2a += acc[mf][nf][0] * a2v[nf*2] + acc[mf][nf][1] * a2v[nf*2+1];
                s1b += acc[mf][nf][2] * a1v[nf*2] + acc[mf][nf][3] * a1v[nf*2+1];
                s2b += acc[mf][nf][2] * a2v[nf*2] + acc[mf][nf][3] * a2v[nf*2+1];
            }
            #pragma unroll
            for (int off = 1; off <= 2; off <<= 1) {
                s1a += __shfl_xor_sync(0xFFFFFFFFu, s1a, off);
                s2a += __shfl_xor_sync(0xFFFFFFFFu, s2a, off);
                s1b += __shfl_xor_sync(0xFFFFFFFFu, s1b, off);
                s2b += __shfl_xor_sync(0xFFFFFFFFu, s2b, off);
            }
            if ((lane & 3) == 0) {
                int rA = rowBase + wm * 32 + mf * 16 + (lane >> 2);
                atomicAdd(&g_as[rA],     s1a);  atomicAdd(&g_an[rA],     s2a);
                atomicAdd(&g_as[rA + 8], s1b);  atomicAdd(&g_an[rA + 8], s2b);
            }
        }
        // ---- transpose via smem, hi/lo split, coalesced store ----
        float* sm = (float*)dbase;                 // [64][SMP] f32 = 34 KB
        __syncthreads();                           // mainloop smem reads done
        #pragma unroll
        for (int mf = 0; mf < 2; mf++) {
            int r = wm * 32 + mf * 16 + (lane >> 2);
            int c = wn * 32 + (lane & 3) * 2;
            #pragma unroll
            for (int nf = 0; nf < 4; nf++) {
                sm[r * SMP + c + nf*8]           = acc[mf][nf][0];
                sm[r * SMP + c + nf*8 + 1]       = acc[mf][nf][1];
                sm[(r + 8) * SMP + c + nf*8]     = acc[mf][nf][2];
                sm[(r + 8) * SMP + c + nf*8 + 1] = acc[mf][nf][3];
            }
        }
        __syncthreads();
        const int bb = rowBase >> 12;
        const int mbase = rowBase & (NN - 1);
        uint32_t* dh = (uint32_t*)(g_hth + (size_t)bb * FOUT * NN);
        uint32_t* dl = (uint32_t*)(g_htl + (size_t)bb * FOUT * NN);
        for (int idx = tid; idx < 128 * 32; idx += NT) {
            int n = idx >> 5, mp = idx & 31;
            float v0 = sm[(2*mp)     * SMP + n];
            float v1 = sm[(2*mp + 1) * SMP + n];
            uint32_t hp, lp;
            split2(v0, v1, hp, lp);
            size_t o = (((size_t)(colBase + n) * NN + mbase) >> 1) + mp;
            dh[o] = hp;
            dl[o] = lp;
        }
    }
}

// ================= K0a: x hi/lo bf16 split (elementwise) =================
__global__ __launch_bounds__(256) void xsplit(const float* __restrict__ x) {
    int idx = blockIdx.x * 256 + threadIdx.x;     // over BB*NN*FIN/4
    float4 v = ((const float4*)x)[idx];
    uint32_t h01, l01, h23, l23;
    split2(v.x, v.y, h01, l01);
    split2(v.z, v.w, h23, l23);
    ((uint2*)g_xh)[idx] = make_uint2(h01, h23);
    ((uint2*)g_xl)[idx] = make_uint2(l01, l23);
}

// ================= K0b: W^T hi/lo bf16 split + zero attn accumulators ======
__global__ __launch_bounds__(256) void wsplit(const float* __restrict__ W) {
    __shared__ float tile[32][33];
    const int k0 = blockIdx.x * 32, n0 = blockIdx.y * 32;
    const int tx = threadIdx.x, ty = threadIdx.y;
    const int tid = ty * 32 + tx;
    {
        int bid = blockIdx.y * 16 + blockIdx.x;
        if (tid < 128) {
            int i = bid * 128 + tid;
            g_as[i] = 0.f;
            g_an[i] = 0.f;
        }
    }
    #pragma unroll
    for (int r = 0; r < 4; r++)
        tile[ty + r*8][tx] = W[(size_t)(k0 + ty + r*8) * FOUT + n0 + tx];
    __syncthreads();
    #pragma unroll
    for (int r = 0; r < 4; r++) {
        float v = tile[tx][ty + r*8];   // W[k0+tx][n0+ty+r*8]
        __nv_bfloat16 hi = __float2bfloat16_rn(v);
        __nv_bfloat16 lo = __float2bfloat16_rn(v - __bfloat162float(hi));
        size_t o = (size_t)(n0 + ty + r*8) * FIN + k0 + tx;
        g_wth[o] = hi; g_wtl[o] = lo;
    }
}

// ================= K3: masked LeakyReLU + row softmax (+ bf16 hi/lo P) =====
#define RPB 8
__global__ __launch_bounds__(256) void softmax_rows(const int* __restrict__ adj,
                                                    float* __restrict__ scores) {
    const int row0 = blockIdx.x * RPB;    // global row in [0, BB*NN)
    const int b = row0 >> 12;
    __shared__ float s_an[NN];            // 16 KB
    __shared__ float red[16];
    const int tid = threadIdx.x;
    const int warp = tid >> 5, lane = tid & 31;

    const float4* anb = (const float4*)(g_an + (size_t)b * NN);
    float4* s_an4 = (float4*)s_an;
    for (int j = tid; j < NN / 4; j += 256) s_an4[j] = anb[j];
    __syncthreads();

    for (int rp = 0; rp < RPB; rp += 2) {
        const int rowA = row0 + rp;
        const int rowB = rowA + 1;
        const float asvA = g_as[rowA];
        const float asvB = g_as[rowB];
        const int4* aA4 = (const int4*)(adj + (size_t)rowA * NN);
        const int4* aB4 = (const int4*)(adj + (size_t)rowB * NN);

        float eA[16], eB[16];
        float mA = -3.0e38f, mB = -3.0e38f;
        #pragma unroll
        for (int g = 0; g < 4; g++) {
            int j4 = tid + g * 256;
            int4 a0 = aA4[j4];
            int4 a1 = aB4[j4];
            float4 an = s_an4[j4];
            float t;
            t = asvA + an.x; t = (t >= 0.f) ? t : 0.2f * t; if (a0.x <= 0) t = NEG_BIG; eA[g*4+0] = t; mA = fmaxf(mA, t);
            t = asvA + an.y; t = (t >= 0.f) ? t : 0.2f * t; if (a0.y <= 0) t = NEG_BIG; eA[g*4+1] = t; mA = fmaxf(mA, t);
            t = asvA + an.z; t = (t >= 0.f) ? t : 0.2f * t; if (a0.z <= 0) t = NEG_BIG; eA[g*4+2] = t; mA = fmaxf(mA, t);
            t = asvA + an.w; t = (t >= 0.f) ? t : 0.2f * t; if (a0.w <= 0) t = NEG_BIG; eA[g*4+3] = t; mA = fmaxf(mA, t);
            t = asvB + an.x; t = (t >= 0.f) ? t : 0.2f * t; if (a1.x <= 0) t = NEG_BIG; eB[g*4+0] = t; mB = fmaxf(mB, t);
            t = asvB + an.y; t = (t >= 0.f) ? t : 0.2f * t; if (a1.y <= 0) t = NEG_BIG; eB[g*4+1] = t; mB = fmaxf(mB, t);
            t = asvB + an.z; t = (t >= 0.f) ? t : 0.2f * t; if (a1.z <= 0) t = NEG_BIG; eB[g*4+2] = t; mB = fmaxf(mB, t);
            t = asvB + an.w; t = (t >= 0.f) ? t : 0.2f * t; if (a1.w <= 0) t = NEG_BIG; eB[g*4+3] = t; mB = fmaxf(mB, t);
        }
        #pragma unroll
        for (int off = 16; off; off >>= 1) {
            mA = fmaxf(mA, __shfl_xor_sync(0xFFFFFFFFu, mA, off));
            mB = fmaxf(mB, __shfl_xor_sync(0xFFFFFFFFu, mB, off));
        }
        if (lane == 0) { red[warp] = mA; red[warp + 8] = mB; }
        __syncthreads();
        float MA = red[0], MB = red[8];
        #pragma unroll
        for (int w = 1; w < 8; w++) {
            MA = fmaxf(MA, red[w]);
            MB = fmaxf(MB, red[w + 8]);
        }
        __syncthreads();

        float sA = 0.f, sB = 0.f;
        #pragma unroll
        for (int i = 0; i < 16; i++) {
            float pA = __expf(eA[i] - MA);   // masked lanes underflow to exact 0
            float pB = __expf(eB[i] - MB);
            eA[i] = pA; eB[i] = pB;
            sA += pA; sB += pB;
        }
        #pragma unroll
        for (int off = 16; off; off >>= 1) {
            sA += __shfl_xor_sync(0xFFFFFFFFu, sA, off);
            sB += __shfl_xor_sync(0xFFFFFFFFu, sB, off);
        }
        if (lane == 0) { red[warp] = sA; red[warp + 8] = sB; }
        __syncthreads();
        float SA = red[0], SB = red[8];
        #pragma unroll
        for (int w = 1; w < 8; w++) {
            SA += red[w];
            SB += red[w + 8];
        }
        const float SinvA = 1.0f / SA;
        const float SinvB = 1.0f / SB;

        float4* pA4 = (float4*)(scores + (size_t)rowA * NN);
        float4* pB4 = (float4*)(scores + (size_t)rowB * NN);
        uint2* phA = (uint2*)(g_ph + (size_t)rowA * NN);
        uint2* plA = (uint2*)(g_pl + (size_t)rowA * NN);
        uint2* phB = (uint2*)(g_ph + (size_t)rowB * NN);
        uint2* plB = (uint2*)(g_pl + (size_t)rowB * NN);
        #pragma unroll
        for (int g = 0; g < 4; g++) {
            int j4 = tid + g * 256;
            float4 vA = make_float4(eA[g*4+0] * SinvA, eA[g*4+1] * SinvA,
                                    eA[g*4+2] * SinvA, eA[g*4+3] * SinvA);
            float4 vB = make_float4(eB[g*4+0] * SinvB, eB[g*4+1] * SinvB,
                                    eB[g*4+2] * SinvB, eB[g*4+3] * SinvB);
            pA4[j4] = vA;
            pB4[j4] = vB;
            uint32_t h01, l01, h23, l23;
            split2(vA.x, vA.y, h01, l01);
            split2(vA.z, vA.w, h23, l23);
            phA[j4] = make_uint2(h01, h23);
            plA[j4] = make_uint2(l01, l23);
            split2(vB.x, vB.y, h01, l01);
            split2(vB.z, vB.w, h23, l23);
            phB[j4] = make_uint2(h01, h23);
            plB[j4] = make_uint2(l01, l23);
        }
        __syncthreads();   // red reused next pair
    }
}

// ================= launch =================
extern "C" void kernel_launch(void* const* d_in, const int* in_sizes, int n_in,
                              void* d_out, int out_size) {
    const float* x   = (const float*)d_in[0];   // [B,N,Fin]
    const int*   adj = (const int*)  d_in[1];   // [B,N,N]
    const float* W   = (const float*)d_in[2];   // [Fin,Fout]
    const float* a1  = (const float*)d_in[3];   // [Fout,1]
    const float* a2  = (const float*)d_in[4];   // [Fout,1]

    float* out    = (float*)d_out;                       // [B,N,Fout]
    float* scores = out + (size_t)BB * NN * FOUT;        // [B,N,N]

    __nv_bfloat16 *wth, *wtl, *hth, *htl, *xh, *xl, *ph, *pl;
    cudaGetSymbolAddress((void**)&wth, g_wth);
    cudaGetSymbolAddress((void**)&wtl, g_wtl);
    cudaGetSymbolAddress((void**)&hth, g_hth);
    cudaGetSymbolAddress((void**)&htl, g_htl);
    cudaGetSymbolAddress((void**)&xh,  g_xh);
    cudaGetSymbolAddress((void**)&xl,  g_xl);
    cudaGetSymbolAddress((void**)&ph,  g_ph);
    cudaGetSymbolAddress((void**)&pl,  g_pl);

    const int dynsmem = 2 * STAGE + 1024;   // 99328 -> 2 CTAs/SM
    cudaFuncSetAttribute(mma_gemm<1>, cudaFuncAttributeMaxDynamicSharedMemorySize, dynsmem);
    cudaFuncSetAttribute(mma_gemm<2>, cudaFuncAttributeMaxDynamicSharedMemorySize, dynsmem);

    // K0: x hi/lo split; W^T hi/lo + zero attn accumulators
    xsplit<<<(BB * NN * FIN / 4) / 256, 256>>>(x);
    wsplit<<<dim3(FIN / 32, FOUT / 32), dim3(32, 8)>>>(W);
    // K1: h = x @ W (tensor) -> fused h^T hi/lo + attn dots
    mma_gemm<2><<<dim3((BB * NN) / 64, 2, 1), NT, dynsmem>>>(
        xh, xl, wth, wtl, nullptr, FIN, 0, 0, 0, a1, a2);
    // K3: masked softmax -> scores f32 (second output) + P hi/lo bf16
    softmax_rows<<<(BB * NN) / RPB, 256>>>(adj, scores);
    // K4: h_prime = P @ h (tensor), ELU -> out
    mma_gemm<1><<<dim3(NN / 64, 2, BB), NT, dynsmem>>>(
        ph, pl, hth, htl, out, NN,
        (size_t)NN * NN, (size_t)FOUT * NN, (size_t)NN * FOUT, nullptr, nullptr);
}

// round 15
// speedup vs baseline: 1.3723x; 1.3723x over previous
#include <cuda_runtime.h>
#include <cuda_bf16.h>
#include <cuda_fp16.h>
#include <cstdint>
#include <math.h>

#define BB   4
#define NN   4096
#define FIN  512
#define FOUT 256
#define NEG_BIG (-9.0e15f)

// ---------------- scratch (no allocations allowed) ----------------
__device__ float g_as[BB * NN];                   // attn_self   (atomic-accumulated)
__device__ float g_an[BB * NN];                   // attn_neigh
__device__ __half g_hth[BB * FOUT * NN];          // h^T hi (fp16)  [B,256,4096]
__device__ __half g_htl[BB * FOUT * NN];          // h^T lo (fp16)
__device__ __nv_bfloat16 g_wth[FOUT * FIN];       // W^T hi (bf16)  [256,512]
__device__ __nv_bfloat16 g_wtl[FOUT * FIN];       // W^T lo (bf16)

// ================= helpers =================
__device__ __forceinline__ uint32_t smem_u32(const void* p) {
    uint32_t a;
    asm("{ .reg .u64 t; cvta.to.shared.u64 t, %1; cvt.u32.u64 %0, t; }" : "=r"(a) : "l"(p));
    return a;
}
#define SW128(o) ((o) ^ (((o) >> 3) & 0x70))

__device__ __forceinline__ void cp16(uint32_t dst, const void* src) {
    asm volatile("cp.async.cg.shared.global [%0], [%1], 16;\n" :: "r"(dst), "l"(src));
}
__device__ __forceinline__ void ldsm_x4(uint32_t* r, uint32_t addr) {
    asm volatile("ldmatrix.sync.aligned.m8n8.x4.shared.b16 {%0,%1,%2,%3}, [%4];"
        : "=r"(r[0]), "=r"(r[1]), "=r"(r[2]), "=r"(r[3]) : "r"(addr));
}
__device__ __forceinline__ void mma_bf16(float* d, const uint32_t* a, const uint32_t* b) {
    asm volatile("mma.sync.aligned.m16n8k16.row.col.f32.bf16.bf16.f32 "
        "{%0,%1,%2,%3}, {%4,%5,%6,%7}, {%8,%9}, {%0,%1,%2,%3};"
        : "+f"(d[0]), "+f"(d[1]), "+f"(d[2]), "+f"(d[3])
        : "r"(a[0]), "r"(a[1]), "r"(a[2]), "r"(a[3]), "r"(b[0]), "r"(b[1]));
}
__device__ __forceinline__ void mma_f16(float* d, const uint32_t* a, const uint32_t* b) {
    asm volatile("mma.sync.aligned.m16n8k16.row.col.f32.f16.f16.f32 "
        "{%0,%1,%2,%3}, {%4,%5,%6,%7}, {%8,%9}, {%0,%1,%2,%3};"
        : "+f"(d[0]), "+f"(d[1]), "+f"(d[2]), "+f"(d[3])
        : "r"(a[0]), "r"(a[1]), "r"(a[2]), "r"(a[3]), "r"(b[0]), "r"(b[1]));
}
#define STS64(addr, v0, v1) \
    asm volatile("st.shared.v2.b32 [%0], {%1,%2};" :: "r"(addr), "r"(v0), "r"(v1) : "memory")

// packed hi/lo bf16 split of two floats: hp = bf16x2{lo=x, hi=y}, lp = residuals
__device__ __forceinline__ void split2(float x, float y, uint32_t& hp, uint32_t& lp) {
    asm("cvt.rn.bf16x2.f32 %0, %1, %2;" : "=r"(hp) : "f"(y), "f"(x));
    float lx = x - __uint_as_float(hp << 16);
    float ly = y - __uint_as_float(hp & 0xFFFF0000u);
    asm("cvt.rn.bf16x2.f32 %0, %1, %2;" : "=r"(lp) : "f"(ly), "f"(lx));
}
// fp16 hi/lo split of two floats (x in low half, y in high half)
__device__ __forceinline__ void split2h(float x, float y, uint32_t& hp, uint32_t& lp) {
    __half hx = __float2half_rn(x), hy = __float2half_rn(y);
    __half2 h2 = __halves2half2(hx, hy);
    hp = *(uint32_t*)&h2;
    float lx = x - __half2float(hx), ly = y - __half2float(hy);
    __half2 l2 = __halves2half2(__float2half_rn(lx), __float2half_rn(ly));
    lp = *(uint32_t*)&l2;
}

// ================= generalized mma.sync GEMM =================
// C[b][M,256] = A[b][M,Kdim] @ B[b][256,Kdim]^T
// CTA tile 128(M) x 256(N), K chunk 64. 512 threads, 16 warps 4(M)x4(N),
// warp tile 32x64. 2 smem stages x 96KB.
// MODE 1 (K4): A = f32 scores -> single fp16 in-kernel; B = h^T fp16 hi/lo;
//              2 MMA terms (ah*bh + ah*bl); ELU epilogue -> Cg.
// MODE 2 (K1): A = f32 x -> bf16 hi/lo in-kernel; B = W^T bf16 hi/lo;
//              3 MMA terms; epilogue: h^T fp16 hi/lo + attn dots.
#define KB_CH 64
#define STAGE 98304
#define OAH 0
#define OAL 16384
#define OBH 32768
#define OBL 65536
#define SMP 261   // smem transpose row pitch (floats)
#define NT  512

template<int MODE>
__global__ __launch_bounds__(NT, 1) void mma_gemm(
    const float* __restrict__ Abase, const void* __restrict__ Bh_,
    const void* __restrict__ Bl_, float* __restrict__ Cbase,
    int Kdim, size_t sA, size_t sB, size_t sC,
    const float* __restrict__ att1, const float* __restrict__ att2)
{
    extern __shared__ char dynsmem[];
    const int tid = threadIdx.x;
    const int wid = tid >> 5, lane = tid & 31;
    const int mtile = blockIdx.x, b = blockIdx.y;
    const int rowBase = mtile * 128;
    const int wm = wid >> 2, wn = wid & 3;   // warp tile 32(M) x 64(N)

    uint32_t raw = smem_u32(dynsmem);
    uint32_t sbase = (raw + 1023u) & ~1023u;
    char* dbase = dynsmem + (sbase - raw);

    const float* Ag = Abase + (size_t)b * sA + (size_t)rowBase * Kdim;
    const char* Bhg = (const char*)Bh_ + (size_t)b * sB * 2;
    const char* Blg = (const char*)Bl_ + (size_t)b * sB * 2;
    float* Cg = Cbase + (size_t)b * sC;

    // ldmatrix address components (fixed per thread)
    const uint32_t a_row_l = lane & 15;
    const uint32_t a_k16   = (lane >> 4) * 16;
    const uint32_t a_xor   = (a_row_l & 7) << 4;
    uint32_t a_rowoff[2];
    #pragma unroll
    for (int mf = 0; mf < 2; mf++)
        a_rowoff[mf] = (uint32_t)(wm * 32 + mf * 16 + a_row_l) * 128;

    const uint32_t b_nl  = (lane & 7) + ((lane >> 4) & 1) * 8;
    const uint32_t b_k16 = ((lane >> 3) & 1) * 16;
    const uint32_t b_xor = (b_nl & 7) << 4;
    uint32_t b_rowoff[4];
    #pragma unroll
    for (int np = 0; np < 4; np++)
        b_rowoff[np] = (uint32_t)(wn * 64 + np * 16 + b_nl) * 128;

    float acc[2][8][4] = {};
    float4 av[4];

    // ---- stage-fill lambdas ----
    auto ldA = [&](int kc) {
        #pragma unroll
        for (int l = 0; l < 4; l++) {
            int id = tid + l * NT;
            int r = id >> 4, ch = id & 15;
            av[l] = *(const float4*)(Ag + (size_t)r * Kdim + kc + ch * 4);
        }
    };
    auto stA = [&](uint32_t stb) {
        #pragma unroll
        for (int l = 0; l < 4; l++) {
            int id = tid + l * NT;
            int r = id >> 4, ch = id & 15;
            float4 v = av[l];
            uint32_t sw = SW128((uint32_t)(r * 128 + ch * 8));
            if (MODE == 1) {
                uint32_t h01, h23;   // single fp16
                asm("cvt.rn.f16x2.f32 %0, %1, %2;" : "=r"(h01) : "f"(v.y), "f"(v.x));
                asm("cvt.rn.f16x2.f32 %0, %1, %2;" : "=r"(h23) : "f"(v.w), "f"(v.z));
                STS64(stb + OAH + sw, h01, h23);
            } else {
                uint32_t h01, l01, h23, l23;   // bf16 hi/lo
                split2(v.x, v.y, h01, l01);
                split2(v.z, v.w, h23, l23);
                STS64(stb + OAH + sw, h01, h23);
                STS64(stb + OAL + sw, l01, l23);
            }
        }
    };
    auto cpB = [&](uint32_t stb, int kc) {
        #pragma unroll
        for (int l = 0; l < 4; l++) {
            int id = tid + l * NT;
            int r = id >> 3, ch = id & 7;            // r: 0..255 (full FOUT)
            size_t so = ((size_t)r * Kdim + kc + ch * 8) * 2;   // bytes
            uint32_t sw = SW128((uint32_t)(r * 128 + ch * 16));
            cp16(stb + OBH + sw, Bhg + so);
            cp16(stb + OBL + sw, Blg + so);
        }
    };
    auto compute = [&](uint32_t stb, int ks0, int ks1) {
        #pragma unroll
        for (int ks = ks0; ks < ks1; ks++) {
            uint32_t akt = ((uint32_t)(ks * 32) + a_k16) ^ a_xor;
            uint32_t bkt = ((uint32_t)(ks * 32) + b_k16) ^ b_xor;
            uint32_t ah[2][4], al[2][4];
            #pragma unroll
            for (int mf = 0; mf < 2; mf++) {
                ldsm_x4(ah[mf], stb + OAH + a_rowoff[mf] + akt);
                if (MODE == 2) ldsm_x4(al[mf], stb + OAL + a_rowoff[mf] + akt);
            }
            #pragma unroll
            for (int np = 0; np < 4; np++) {
                uint32_t bh[4], bl[4];
                ldsm_x4(bh, stb + OBH + b_rowoff[np] + bkt);
                ldsm_x4(bl, stb + OBL + b_rowoff[np] + bkt);
                if (MODE == 1) {
                    // 2 terms fp16: ah*bh then ah*bl (per-accumulator order fixed)
                    #pragma unroll
                    for (int mf = 0; mf < 2; mf++) mma_f16(acc[mf][np*2],   ah[mf], &bh[0]);
                    #pragma unroll
                    for (int mf = 0; mf < 2; mf++) mma_f16(acc[mf][np*2+1], ah[mf], &bh[2]);
                    #pragma unroll
                    for (int mf = 0; mf < 2; mf++) mma_f16(acc[mf][np*2],   ah[mf], &bl[0]);
                    #pragma unroll
                    for (int mf = 0; mf < 2; mf++) mma_f16(acc[mf][np*2+1], ah[mf], &bl[2]);
                } else {
                    // 3 terms bf16: ah*bh -> ah*bl -> al*bh
                    #pragma unroll
                    for (int mf = 0; mf < 2; mf++) mma_bf16(acc[mf][np*2],   ah[mf], &bh[0]);
                    #pragma unroll
                    for (int mf = 0; mf < 2; mf++) mma_bf16(acc[mf][np*2+1], ah[mf], &bh[2]);
                    #pragma unroll
                    for (int mf = 0; mf < 2; mf++) mma_bf16(acc[mf][np*2],   ah[mf], &bl[0]);
                    #pragma unroll
                    for (int mf = 0; mf < 2; mf++) mma_bf16(acc[mf][np*2+1], ah[mf], &bl[2]);
                    #pragma unroll
                    for (int mf = 0; mf < 2; mf++) mma_bf16(acc[mf][np*2],   al[mf], &bh[0]);
                    #pragma unroll
                    for (int mf = 0; mf < 2; mf++) mma_bf16(acc[mf][np*2+1], al[mf], &bh[2]);
                }
            }
        }
    };

    // ---- pipeline ----
    ldA(0);
    cpB(sbase, 0);
    asm volatile("cp.async.commit_group;" ::: "memory");
    stA(sbase);
    asm volatile("cp.async.wait_group 0;" ::: "memory");
    __syncthreads();

    const int nch = Kdim / KB_CH;
    int buf = 0;
    for (int c = 0; c < nch; c++) {
        int nb = buf ^ 1;
        bool more = (c + 1 < nch);
        if (more) {
            ldA((c + 1) * KB_CH);
            cpB(sbase + nb * STAGE, (c + 1) * KB_CH);
            asm volatile("cp.async.commit_group;" ::: "memory");
        }
        compute(sbase + buf * STAGE, 0, 2);
        if (more) stA(sbase + nb * STAGE);      // overlaps 2nd compute half
        compute(sbase + buf * STAGE, 2, 4);
        if (more) {
            asm volatile("cp.async.wait_group 0;" ::: "memory");
            __syncthreads();
        }
        buf = nb;
    }

    if (MODE == 1) {
        // ---- ELU + store ----
        #pragma unroll
        for (int mf = 0; mf < 2; mf++) {
            int r0 = rowBase + wm * 32 + mf * 16 + (lane >> 2);
            float* p0 = Cg + (size_t)r0 * FOUT + wn * 64 + (lane & 3) * 2;
            #pragma unroll
            for (int nf = 0; nf < 8; nf++) {
                float* q = p0 + nf * 8;
                float v0 = acc[mf][nf][0], v1 = acc[mf][nf][1];
                float v2 = acc[mf][nf][2], v3 = acc[mf][nf][3];
                v0 = (v0 > 0.f) ? v0 : expm1f(v0);
                v1 = (v1 > 0.f) ? v1 : expm1f(v1);
                v2 = (v2 > 0.f) ? v2 : expm1f(v2);
                v3 = (v3 > 0.f) ? v3 : expm1f(v3);
                *(float2*)q = make_float2(v0, v1);
                *(float2*)(q + 8 * FOUT) = make_float2(v2, v3);
            }
        }
    } else {
        // ---- attn dot partials from fragments ----
        float a1v[16], a2v[16];
        #pragma unroll
        for (int nf = 0; nf < 8; nf++) {
            int c0 = wn * 64 + nf * 8 + (lane & 3) * 2;
            a1v[nf*2+0] = __ldg(att1 + c0);  a1v[nf*2+1] = __ldg(att1 + c0 + 1);
            a2v[nf*2+0] = __ldg(att2 + c0);  a2v[nf*2+1] = __ldg(att2 + c0 + 1);
        }
        #pragma unroll
        for (int mf = 0; mf < 2; mf++) {
            float s1a = 0.f, s2a = 0.f, s1b = 0.f, s2b = 0.f;
            #pragma unroll
            for (int nf = 0; nf < 8; nf++) {
                s1a += acc[mf][nf][0] * a1v[nf*2] + acc[mf][nf][1] * a1v[nf*2+1];
                s2a += acc[mf][nf][0] * a2v[nf*2] + acc[mf][nf][1] * a2v[nf*2+1];
                s1b += acc[mf][nf][2] * a1v[nf*2] + acc[mf][nf][3] * a1v[nf*2+1];
                s2b += acc[mf][nf][2] * a2v[nf*2] + acc[mf][nf][3] * a2v[nf*2+1];
            }
            #pragma unroll
            for (int off = 1; off <= 2; off <<= 1) {
                s1a += __shfl_xor_sync(0xFFFFFFFFu, s1a, off);
                s2a += __shfl_xor_sync(0xFFFFFFFFu, s2a, off);
                s1b += __shfl_xor_sync(0xFFFFFFFFu, s1b, off);
                s2b += __shfl_xor_sync(0xFFFFFFFFu, s2b, off);
            }
            if ((lane & 3) == 0) {
                int rA = rowBase + wm * 32 + mf * 16 + (lane >> 2);
                atomicAdd(&g_as[rA],     s1a);  atomicAdd(&g_an[rA],     s2a);
                atomicAdd(&g_as[rA + 8], s1b);  atomicAdd(&g_an[rA + 8], s2b);
            }
        }
        // ---- transpose via smem, fp16 hi/lo split, coalesced store ----
        float* sm = (float*)dbase;                 // [128][SMP] f32 = 130.5 KB
        __syncthreads();                           // mainloop smem reads done
        #pragma unroll
        for (int mf = 0; mf < 2; mf++) {
            int r = wm * 32 + mf * 16 + (lane >> 2);
            int c = wn * 64 + (lane & 3) * 2;
            #pragma unroll
            for (int nf = 0; nf < 8; nf++) {
                sm[r * SMP + c + nf*8]           = acc[mf][nf][0];
                sm[r * SMP + c + nf*8 + 1]       = acc[mf][nf][1];
                sm[(r + 8) * SMP + c + nf*8]     = acc[mf][nf][2];
                sm[(r + 8) * SMP + c + nf*8 + 1] = acc[mf][nf][3];
            }
        }
        __syncthreads();
        const int bb = rowBase >> 12;
        const int mbase = rowBase & (NN - 1);
        uint32_t* dh = (uint32_t*)(g_hth + (size_t)bb * FOUT * NN);
        uint32_t* dl = (uint32_t*)(g_htl + (size_t)bb * FOUT * NN);
        for (int idx = tid; idx < FOUT * 64; idx += NT) {
            int n = idx >> 6, mp = idx & 63;
            float v0 = sm[(2*mp)     * SMP + n];
            float v1 = sm[(2*mp + 1) * SMP + n];
            uint32_t hp, lp;
            split2h(v0, v1, hp, lp);
            size_t o = (((size_t)n * NN + mbase) >> 1) + mp;
            dh[o] = hp;
            dl[o] = lp;
        }
    }
}

// ================= K0: W^T hi/lo bf16 split + zero attn accumulators =======
__global__ __launch_bounds__(256) void wsplit(const float* __restrict__ W) {
    __shared__ float tile[32][33];
    const int k0 = blockIdx.x * 32, n0 = blockIdx.y * 32;
    const int tx = threadIdx.x, ty = threadIdx.y;
    const int tid = ty * 32 + tx;
    {
        int bid = blockIdx.y * 16 + blockIdx.x;
        if (tid < 128) {
            int i = bid * 128 + tid;
            g_as[i] = 0.f;
            g_an[i] = 0.f;
        }
    }
    #pragma unroll
    for (int r = 0; r < 4; r++)
        tile[ty + r*8][tx] = W[(size_t)(k0 + ty + r*8) * FOUT + n0 + tx];
    __syncthreads();
    #pragma unroll
    for (int r = 0; r < 4; r++) {
        float v = tile[tx][ty + r*8];   // W[k0+tx][n0+ty+r*8]
        __nv_bfloat16 hi = __float2bfloat16_rn(v);
        __nv_bfloat16 lo = __float2bfloat16_rn(v - __bfloat162float(hi));
        size_t o = (size_t)(n0 + ty + r*8) * FIN + k0 + tx;
        g_wth[o] = hi; g_wtl[o] = lo;
    }
}

// ================= K3: masked LeakyReLU + row softmax =================
#define RPB 8
__global__ __launch_bounds__(256) void softmax_rows(const int* __restrict__ adj,
                                                    float* __restrict__ scores) {
    const int row0 = blockIdx.x * RPB;    // global row in [0, BB*NN)
    const int b = row0 >> 12;
    __shared__ float s_an[NN];            // 16 KB
    __shared__ float red[16];
    const int tid = threadIdx.x;
    const int warp = tid >> 5, lane = tid & 31;

    const float4* anb = (const float4*)(g_an + (size_t)b * NN);
    float4* s_an4 = (float4*)s_an;
    for (int j = tid; j < NN / 4; j += 256) s_an4[j] = anb[j];
    __syncthreads();

    for (int rp = 0; rp < RPB; rp += 2) {
        const int rowA = row0 + rp;
        const int rowB = rowA + 1;
        const float asvA = g_as[rowA];
        const float asvB = g_as[rowB];
        const int4* aA4 = (const int4*)(adj + (size_t)rowA * NN);
        const int4* aB4 = (const int4*)(adj + (size_t)rowB * NN);

        float eA[16], eB[16];
        float mA = -3.0e38f, mB = -3.0e38f;
        #pragma unroll
        for (int g = 0; g < 4; g++) {
            int j4 = tid + g * 256;
            int4 a0 = aA4[j4];
            int4 a1 = aB4[j4];
            float4 an = s_an4[j4];
            float t;
            t = asvA + an.x; t = (t >= 0.f) ? t : 0.2f * t; if (a0.x <= 0) t = NEG_BIG; eA[g*4+0] = t; mA = fmaxf(mA, t);
            t = asvA + an.y; t = (t >= 0.f) ? t : 0.2f * t; if (a0.y <= 0) t = NEG_BIG; eA[g*4+1] = t; mA = fmaxf(mA, t);
            t = asvA + an.z; t = (t >= 0.f) ? t : 0.2f * t; if (a0.z <= 0) t = NEG_BIG; eA[g*4+2] = t; mA = fmaxf(mA, t);
            t = asvA + an.w; t = (t >= 0.f) ? t : 0.2f * t; if (a0.w <= 0) t = NEG_BIG; eA[g*4+3] = t; mA = fmaxf(mA, t);
            t = asvB + an.x; t = (t >= 0.f) ? t : 0.2f * t; if (a1.x <= 0) t = NEG_BIG; eB[g*4+0] = t; mB = fmaxf(mB, t);
            t = asvB + an.y; t = (t >= 0.f) ? t : 0.2f * t; if (a1.y <= 0) t = NEG_BIG; eB[g*4+1] = t; mB = fmaxf(mB, t);
            t = asvB + an.z; t = (t >= 0.f) ? t : 0.2f * t; if (a1.z <= 0) t = NEG_BIG; eB[g*4+2] = t; mB = fmaxf(mB, t);
            t = asvB + an.w; t = (t >= 0.f) ? t : 0.2f * t; if (a1.w <= 0) t = NEG_BIG; eB[g*4+3] = t; mB = fmaxf(mB, t);
        }
        #pragma unroll
        for (int off = 16; off; off >>= 1) {
            mA = fmaxf(mA, __shfl_xor_sync(0xFFFFFFFFu, mA, off));
            mB = fmaxf(mB, __shfl_xor_sync(0xFFFFFFFFu, mB, off));
        }
        if (lane == 0) { red[warp] = mA; red[warp + 8] = mB; }
        __syncthreads();
        float MA = red[0], MB = red[8];
        #pragma unroll
        for (int w = 1; w < 8; w++) {
            MA = fmaxf(MA, red[w]);
            MB = fmaxf(MB, red[w + 8]);
        }
        __syncthreads();

        float sA = 0.f, sB = 0.f;
        #pragma unroll
        for (int i = 0; i < 16; i++) {
            float pA = __expf(eA[i] - MA);   // masked lanes underflow to exact 0
            float pB = __expf(eB[i] - MB);
            eA[i] = pA; eB[i] = pB;
            sA += pA; sB += pB;
        }
        #pragma unroll
        for (int off = 16; off; off >>= 1) {
            sA += __shfl_xor_sync(0xFFFFFFFFu, sA, off);
            sB += __shfl_xor_sync(0xFFFFFFFFu, sB, off);
        }
        if (lane == 0) { red[warp] = sA; red[warp + 8] = sB; }
        __syncthreads();
        float SA = red[0], SB = red[8];
        #pragma unroll
        for (int w = 1; w < 8; w++) {
            SA += red[w];
            SB += red[w + 8];
        }
        const float SinvA = 1.0f / SA;
        const float SinvB = 1.0f / SB;

        float4* pA4 = (float4*)(scores + (size_t)rowA * NN);
        float4* pB4 = (float4*)(scores + (size_t)rowB * NN);
        #pragma unroll
        for (int g = 0; g < 4; g++) {
            int j4 = tid + g * 256;
            pA4[j4] = make_float4(eA[g*4+0] * SinvA, eA[g*4+1] * SinvA,
                                  eA[g*4+2] * SinvA, eA[g*4+3] * SinvA);
            pB4[j4] = make_float4(eB[g*4+0] * SinvB, eB[g*4+1] * SinvB,
                                  eB[g*4+2] * SinvB, eB[g*4+3] * SinvB);
        }
        __syncthreads();   // red reused next pair
    }
}

// ================= launch =================
extern "C" void kernel_launch(void* const* d_in, const int* in_sizes, int n_in,
                              void* d_out, int out_size) {
    const float* x   = (const float*)d_in[0];   // [B,N,Fin]
    const int*   adj = (const int*)  d_in[1];   // [B,N,N]
    const float* W   = (const float*)d_in[2];   // [Fin,Fout]
    const float* a1  = (const float*)d_in[3];   // [Fout,1]
    const float* a2  = (const float*)d_in[4];   // [Fout,1]

    float* out    = (float*)d_out;                       // [B,N,Fout]
    float* scores = out + (size_t)BB * NN * FOUT;        // [B,N,N]

    void *wth, *wtl, *hth, *htl;
    cudaGetSymbolAddress(&wth, g_wth);
    cudaGetSymbolAddress(&wtl, g_wtl);
    cudaGetSymbolAddress(&hth, g_hth);
    cudaGetSymbolAddress(&htl, g_htl);

    const int dynsmem = 2 * STAGE + 1024;   // 197632
    cudaFuncSetAttribute(mma_gemm<1>, cudaFuncAttributeMaxDynamicSharedMemorySize, dynsmem);
    cudaFuncSetAttribute(mma_gemm<2>, cudaFuncAttributeMaxDynamicSharedMemorySize, dynsmem);

    // K0: W^T hi/lo + zero attn accumulators (fused)
    wsplit<<<dim3(FIN / 32, FOUT / 32), dim3(32, 8)>>>(W);
    // K1: h = x @ W (bf16 3-term) -> fused h^T fp16 hi/lo + attn dots
    mma_gemm<2><<<dim3((BB * NN) / 128, 1), NT, dynsmem>>>(
        x, wth, wtl, nullptr, FIN, 0, 0, 0, a1, a2);
    // K3: masked softmax -> scores (second output)
    softmax_rows<<<(BB * NN) / RPB, 256>>>(adj, scores);
    // K4: h_prime = P @ h (fp16 2-term), ELU -> out
    mma_gemm<1><<<dim3(NN / 128, BB), NT, dynsmem>>>(
        scores, hth, htl, out, NN,
        (size_t)NN * NN, (size_t)FOUT * NN, (size_t)NN * FOUT, nullptr, nullptr);
}

// round 16
// speedup vs baseline: 1.7410x; 1.2687x over previous
#include <cuda_runtime.h>
#include <cuda_bf16.h>
#include <cuda_fp16.h>
#include <cstdint>
#include <math.h>

#define BB   4
#define NN   4096
#define FIN  512
#define FOUT 256
#define NEG_BIG (-9.0e15f)

// ---------------- scratch (no allocations allowed) ----------------
__device__ float g_as[BB * NN];                   // attn_self   (atomic-accumulated)
__device__ float g_an[BB * NN];                   // attn_neigh
__device__ __half g_hth[BB * FOUT * NN];          // h^T (fp16)  [B,256,4096]
__device__ __nv_bfloat16 g_wth[FOUT * FIN];       // W^T hi (bf16)  [256,512]
__device__ __nv_bfloat16 g_wtl[FOUT * FIN];       // W^T lo (bf16)

// ================= helpers =================
__device__ __forceinline__ uint32_t smem_u32(const void* p) {
    uint32_t a;
    asm("{ .reg .u64 t; cvta.to.shared.u64 t, %1; cvt.u32.u64 %0, t; }" : "=r"(a) : "l"(p));
    return a;
}
#define SW128(o) ((o) ^ (((o) >> 3) & 0x70))

__device__ __forceinline__ void cp16(uint32_t dst, const void* src) {
    asm volatile("cp.async.cg.shared.global [%0], [%1], 16;\n" :: "r"(dst), "l"(src));
}
__device__ __forceinline__ void ldsm_x4(uint32_t* r, uint32_t addr) {
    asm volatile("ldmatrix.sync.aligned.m8n8.x4.shared.b16 {%0,%1,%2,%3}, [%4];"
        : "=r"(r[0]), "=r"(r[1]), "=r"(r[2]), "=r"(r[3]) : "r"(addr));
}
__device__ __forceinline__ void mma_bf16(float* d, const uint32_t* a, const uint32_t* b) {
    asm volatile("mma.sync.aligned.m16n8k16.row.col.f32.bf16.bf16.f32 "
        "{%0,%1,%2,%3}, {%4,%5,%6,%7}, {%8,%9}, {%0,%1,%2,%3};"
        : "+f"(d[0]), "+f"(d[1]), "+f"(d[2]), "+f"(d[3])
        : "r"(a[0]), "r"(a[1]), "r"(a[2]), "r"(a[3]), "r"(b[0]), "r"(b[1]));
}
__device__ __forceinline__ void mma_f16(float* d, const uint32_t* a, const uint32_t* b) {
    asm volatile("mma.sync.aligned.m16n8k16.row.col.f32.f16.f16.f32 "
        "{%0,%1,%2,%3}, {%4,%5,%6,%7}, {%8,%9}, {%0,%1,%2,%3};"
        : "+f"(d[0]), "+f"(d[1]), "+f"(d[2]), "+f"(d[3])
        : "r"(a[0]), "r"(a[1]), "r"(a[2]), "r"(a[3]), "r"(b[0]), "r"(b[1]));
}
#define STS64(addr, v0, v1) \
    asm volatile("st.shared.v2.b32 [%0], {%1,%2};" :: "r"(addr), "r"(v0), "r"(v1) : "memory")

// packed hi/lo bf16 split of two floats: hp = bf16x2{lo=x, hi=y}, lp = residuals
__device__ __forceinline__ void split2(float x, float y, uint32_t& hp, uint32_t& lp) {
    asm("cvt.rn.bf16x2.f32 %0, %1, %2;" : "=r"(hp) : "f"(y), "f"(x));
    float lx = x - __uint_as_float(hp << 16);
    float ly = y - __uint_as_float(hp & 0xFFFF0000u);
    asm("cvt.rn.bf16x2.f32 %0, %1, %2;" : "=r"(lp) : "f"(ly), "f"(lx));
}
__device__ __forceinline__ uint32_t packh2(float x, float y) {
    uint32_t h;
    asm("cvt.rn.f16x2.f32 %0, %1, %2;" : "=r"(h) : "f"(y), "f"(x));
    return h;
}

// ================= generalized mma.sync GEMM =================
// C[b][M,256] = A[b][M,Kdim] @ B[b][256,Kdim]^T
// CTA tile 128(M) x 256(N), 512 threads, 16 warps 4(M)x4(N), warp tile 32x64.
// 2 smem stages x 96KB.
// MODE 1 (K4): A = f32 scores -> single fp16; B = h^T single fp16; 1 MMA term;
//              K chunk 128 (two 64-wide sub-tiles); ELU epilogue -> Cg.
// MODE 2 (K1): A = f32 x -> bf16 hi/lo; B = W^T bf16 hi/lo; 3 MMA terms;
//              K chunk 64; epilogue: h^T single fp16 + attn dots.
#define STAGE 98304
#define SMP 261   // smem transpose row pitch (floats)
#define NT  512

template<int MODE>
__global__ __launch_bounds__(NT, 1) void mma_gemm(
    const float* __restrict__ Abase, const void* __restrict__ Bh_,
    const void* __restrict__ Bl_, float* __restrict__ Cbase,
    int Kdim, size_t sA, size_t sB, size_t sC,
    const float* __restrict__ att1, const float* __restrict__ att2)
{
    constexpr int KCH = (MODE == 1) ? 128 : 64;
    constexpr int NKS = KCH / 16;                 // k-steps per chunk (8 / 4)
    // MODE1 layout: A fp16 2x16KB subtiles @0; B fp16 2x32KB subtiles @32768
    // MODE2 layout: A bf16 hi @0, lo @16384; B bf16 hi @32768, lo @65536
    constexpr uint32_t OAL_ = 16384, OBH_ = 32768, OBL_ = 65536;

    extern __shared__ char dynsmem[];
    const int tid = threadIdx.x;
    const int wid = tid >> 5, lane = tid & 31;
    const int mtile = blockIdx.x, b = blockIdx.y;
    const int rowBase = mtile * 128;
    const int wm = wid >> 2, wn = wid & 3;   // warp tile 32(M) x 64(N)

    uint32_t raw = smem_u32(dynsmem);
    uint32_t sbase = (raw + 1023u) & ~1023u;
    char* dbase = dynsmem + (sbase - raw);

    const float* Ag = Abase + (size_t)b * sA + (size_t)rowBase * Kdim;
    const char* Bhg = (const char*)Bh_ + (size_t)b * sB * 2;
    const char* Blg = (const char*)Bl_ + (size_t)b * sB * 2;
    float* Cg = Cbase + (size_t)b * sC;

    // ldmatrix address components (fixed per thread)
    const uint32_t a_row_l = lane & 15;
    const uint32_t a_k16   = (lane >> 4) * 16;
    const uint32_t a_xor   = (a_row_l & 7) << 4;
    uint32_t a_rowoff[2];
    #pragma unroll
    for (int mf = 0; mf < 2; mf++)
        a_rowoff[mf] = (uint32_t)(wm * 32 + mf * 16 + a_row_l) * 128;

    const uint32_t b_nl  = (lane & 7) + ((lane >> 4) & 1) * 8;
    const uint32_t b_k16 = ((lane >> 3) & 1) * 16;
    const uint32_t b_xor = (b_nl & 7) << 4;
    uint32_t b_rowoff[4];
    #pragma unroll
    for (int np = 0; np < 4; np++)
        b_rowoff[np] = (uint32_t)(wn * 64 + np * 16 + b_nl) * 128;

    float acc[2][8][4] = {};
    float4 av[8];

    // ---- stage-fill lambdas ----
    auto ldA = [&](int kc) {
        if (MODE == 1) {
            // 128 rows x 128 k f32: 4096 float4, 8 per thread
            #pragma unroll
            for (int l = 0; l < 8; l++) {
                int id = tid + l * NT;
                int r = id >> 5, ch = id & 31;
                av[l] = *(const float4*)(Ag + (size_t)r * Kdim + kc + ch * 4);
            }
        } else {
            // 128 rows x 64 k f32: 2048 float4, 4 per thread
            #pragma unroll
            for (int l = 0; l < 4; l++) {
                int id = tid + l * NT;
                int r = id >> 4, ch = id & 15;
                av[l] = *(const float4*)(Ag + (size_t)r * Kdim + kc + ch * 4);
            }
        }
    };
    auto stA = [&](uint32_t stb) {
        if (MODE == 1) {
            #pragma unroll
            for (int l = 0; l < 8; l++) {
                int id = tid + l * NT;
                int r = id >> 5, ch = id & 31;
                float4 v = av[l];
                uint32_t h01 = packh2(v.x, v.y);
                uint32_t h23 = packh2(v.z, v.w);
                uint32_t sub = (uint32_t)(ch >> 4);
                uint32_t sw = SW128((uint32_t)(r * 128 + (ch & 15) * 8));
                STS64(stb + sub * 16384 + sw, h01, h23);
            }
        } else {
            #pragma unroll
            for (int l = 0; l < 4; l++) {
                int id = tid + l * NT;
                int r = id >> 4, ch = id & 15;
                float4 v = av[l];
                uint32_t h01, l01, h23, l23;
                split2(v.x, v.y, h01, l01);
                split2(v.z, v.w, h23, l23);
                uint32_t sw = SW128((uint32_t)(r * 128 + ch * 8));
                STS64(stb + sw, h01, h23);
                STS64(stb + OAL_ + sw, l01, l23);
            }
        }
    };
    auto cpB = [&](uint32_t stb, int kc) {
        if (MODE == 1) {
            // B fp16: 256 rows x 128 k = 4096 x 16B, 8 per thread
            #pragma unroll
            for (int l = 0; l < 8; l++) {
                int id = tid + l * NT;
                int r = id >> 4, ch = id & 15;
                size_t so = ((size_t)r * Kdim + kc + ch * 8) * 2;   // bytes
                uint32_t sub = (uint32_t)(ch >> 3);
                uint32_t sw = SW128((uint32_t)(r * 128 + (ch & 7) * 16));
                cp16(stb + OBH_ + sub * 32768 + sw, Bhg + so);
            }
        } else {
            #pragma unroll
            for (int l = 0; l < 4; l++) {
                int id = tid + l * NT;
                int r = id >> 3, ch = id & 7;
                size_t so = ((size_t)r * Kdim + kc + ch * 8) * 2;   // bytes
                uint32_t sw = SW128((uint32_t)(r * 128 + ch * 16));
                cp16(stb + OBH_ + sw, Bhg + so);
                cp16(stb + OBL_ + sw, Blg + so);
            }
        }
    };
    auto compute = [&](uint32_t stb, int ks0, int ks1) {
        #pragma unroll
        for (int ks = ks0; ks < ks1; ks++) {
            if (MODE == 1) {
                uint32_t kk = (uint32_t)(ks >> 2), k4 = (uint32_t)(ks & 3);
                uint32_t akt = kk * 16384 + ((k4 * 32 + a_k16) ^ a_xor);
                uint32_t bkt = OBH_ + kk * 32768 + ((k4 * 32 + b_k16) ^ b_xor);
                uint32_t ah[2][4];
                #pragma unroll
                for (int mf = 0; mf < 2; mf++)
                    ldsm_x4(ah[mf], stb + a_rowoff[mf] + akt);
                #pragma unroll
                for (int np = 0; np < 4; np++) {
                    uint32_t bh[4];
                    ldsm_x4(bh, stb + bkt + b_rowoff[np]);
                    #pragma unroll
                    for (int mf = 0; mf < 2; mf++) mma_f16(acc[mf][np*2],   ah[mf], &bh[0]);
                    #pragma unroll
                    for (int mf = 0; mf < 2; mf++) mma_f16(acc[mf][np*2+1], ah[mf], &bh[2]);
                }
            } else {
                uint32_t akt = ((uint32_t)(ks * 32) + a_k16) ^ a_xor;
                uint32_t bkt = ((uint32_t)(ks * 32) + b_k16) ^ b_xor;
                uint32_t ah[2][4], al[2][4];
                #pragma unroll
                for (int mf = 0; mf < 2; mf++) {
                    ldsm_x4(ah[mf], stb + a_rowoff[mf] + akt);
                    ldsm_x4(al[mf], stb + OAL_ + a_rowoff[mf] + akt);
                }
                #pragma unroll
                for (int np = 0; np < 4; np++) {
                    uint32_t bh[4], bl[4];
                    ldsm_x4(bh, stb + OBH_ + b_rowoff[np] + bkt);
                    ldsm_x4(bl, stb + OBL_ + b_rowoff[np] + bkt);
                    // per-accumulator term order ah*bh -> ah*bl -> al*bh
                    #pragma unroll
                    for (int mf = 0; mf < 2; mf++) mma_bf16(acc[mf][np*2],   ah[mf], &bh[0]);
                    #pragma unroll
                    for (int mf = 0; mf < 2; mf++) mma_bf16(acc[mf][np*2+1], ah[mf], &bh[2]);
                    #pragma unroll
                    for (int mf = 0; mf < 2; mf++) mma_bf16(acc[mf][np*2],   ah[mf], &bl[0]);
                    #pragma unroll
                    for (int mf = 0; mf < 2; mf++) mma_bf16(acc[mf][np*2+1], ah[mf], &bl[2]);
                    #pragma unroll
                    for (int mf = 0; mf < 2; mf++) mma_bf16(acc[mf][np*2],   al[mf], &bh[0]);
                    #pragma unroll
                    for (int mf = 0; mf < 2; mf++) mma_bf16(acc[mf][np*2+1], al[mf], &bh[2]);
                }
            }
        }
    };

    // ---- pipeline ----
    ldA(0);
    cpB(sbase, 0);
    asm volatile("cp.async.commit_group;" ::: "memory");
    stA(sbase);
    asm volatile("cp.async.wait_group 0;" ::: "memory");
    __syncthreads();

    const int nch = Kdim / KCH;
    int buf = 0;
    for (int c = 0; c < nch; c++) {
        int nb = buf ^ 1;
        bool more = (c + 1 < nch);
        if (more) {
            ldA((c + 1) * KCH);
            cpB(sbase + nb * STAGE, (c + 1) * KCH);
            asm volatile("cp.async.commit_group;" ::: "memory");
        }
        compute(sbase + buf * STAGE, 0, NKS / 2);
        if (more) stA(sbase + nb * STAGE);      // overlaps 2nd compute half
        compute(sbase + buf * STAGE, NKS / 2, NKS);
        if (more) {
            asm volatile("cp.async.wait_group 0;" ::: "memory");
            __syncthreads();
        }
        buf = nb;
    }

    if (MODE == 1) {
        // ---- ELU + store ----
        #pragma unroll
        for (int mf = 0; mf < 2; mf++) {
            int r0 = rowBase + wm * 32 + mf * 16 + (lane >> 2);
            float* p0 = Cg + (size_t)r0 * FOUT + wn * 64 + (lane & 3) * 2;
            #pragma unroll
            for (int nf = 0; nf < 8; nf++) {
                float* q = p0 + nf * 8;
                float v0 = acc[mf][nf][0], v1 = acc[mf][nf][1];
                float v2 = acc[mf][nf][2], v3 = acc[mf][nf][3];
                v0 = (v0 > 0.f) ? v0 : expm1f(v0);
                v1 = (v1 > 0.f) ? v1 : expm1f(v1);
                v2 = (v2 > 0.f) ? v2 : expm1f(v2);
                v3 = (v3 > 0.f) ? v3 : expm1f(v3);
                *(float2*)q = make_float2(v0, v1);
                *(float2*)(q + 8 * FOUT) = make_float2(v2, v3);
            }
        }
    } else {
        // ---- attn dot partials from fragments ----
        float a1v[16], a2v[16];
        #pragma unroll
        for (int nf = 0; nf < 8; nf++) {
            int c0 = wn * 64 + nf * 8 + (lane & 3) * 2;
            a1v[nf*2+0] = __ldg(att1 + c0);  a1v[nf*2+1] = __ldg(att1 + c0 + 1);
            a2v[nf*2+0] = __ldg(att2 + c0);  a2v[nf*2+1] = __ldg(att2 + c0 + 1);
        }
        #pragma unroll
        for (int mf = 0; mf < 2; mf++) {
            float s1a = 0.f, s2a = 0.f, s1b = 0.f, s2b = 0.f;
            #pragma unroll
            for (int nf = 0; nf < 8; nf++) {
                s1a += acc[mf][nf][0] * a1v[nf*2] + acc[mf][nf][1] * a1v[nf*2+1];
                s2a += acc[mf][nf][0] * a2v[nf*2] + acc[mf][nf][1] * a2v[nf*2+1];
                s1b += acc[mf][nf][2] * a1v[nf*2] + acc[mf][nf][3] * a1v[nf*2+1];
                s2b += acc[mf][nf][2] * a2v[nf*2] + acc[mf][nf][3] * a2v[nf*2+1];
            }
            #pragma unroll
            for (int off = 1; off <= 2; off <<= 1) {
                s1a += __shfl_xor_sync(0xFFFFFFFFu, s1a, off);
                s2a += __shfl_xor_sync(0xFFFFFFFFu, s2a, off);
                s1b += __shfl_xor_sync(0xFFFFFFFFu, s1b, off);
                s2b += __shfl_xor_sync(0xFFFFFFFFu, s2b, off);
            }
            if ((lane & 3) == 0) {
                int rA = rowBase + wm * 32 + mf * 16 + (lane >> 2);
                atomicAdd(&g_as[rA],     s1a);  atomicAdd(&g_an[rA],     s2a);
                atomicAdd(&g_as[rA + 8], s1b);  atomicAdd(&g_an[rA + 8], s2b);
            }
        }
        // ---- transpose via smem, single fp16, coalesced store ----
        float* sm = (float*)dbase;                 // [128][SMP] f32 = 130.5 KB
        __syncthreads();                           // mainloop smem reads done
        #pragma unroll
        for (int mf = 0; mf < 2; mf++) {
            int r = wm * 32 + mf * 16 + (lane >> 2);
            int c = wn * 64 + (lane & 3) * 2;
            #pragma unroll
            for (int nf = 0; nf < 8; nf++) {
                sm[r * SMP + c + nf*8]           = acc[mf][nf][0];
                sm[r * SMP + c + nf*8 + 1]       = acc[mf][nf][1];
                sm[(r + 8) * SMP + c + nf*8]     = acc[mf][nf][2];
                sm[(r + 8) * SMP + c + nf*8 + 1] = acc[mf][nf][3];
            }
        }
        __syncthreads();
        const int bb = rowBase >> 12;
        const int mbase = rowBase & (NN - 1);
        uint32_t* dh = (uint32_t*)(g_hth + (size_t)bb * FOUT * NN);
        for (int idx = tid; idx < FOUT * 64; idx += NT) {
            int n = idx >> 6, mp = idx & 63;
            float v0 = sm[(2*mp)     * SMP + n];
            float v1 = sm[(2*mp + 1) * SMP + n];
            size_t o = (((size_t)n * NN + mbase) >> 1) + mp;
            dh[o] = packh2(v0, v1);
        }
    }
}

// ================= K0: W^T hi/lo bf16 split + zero attn accumulators =======
__global__ __launch_bounds__(256) void wsplit(const float* __restrict__ W) {
    __shared__ float tile[32][33];
    const int k0 = blockIdx.x * 32, n0 = blockIdx.y * 32;
    const int tx = threadIdx.x, ty = threadIdx.y;
    const int tid = ty * 32 + tx;
    {
        int bid = blockIdx.y * 16 + blockIdx.x;
        if (tid < 128) {
            int i = bid * 128 + tid;
            g_as[i] = 0.f;
            g_an[i] = 0.f;
        }
    }
    #pragma unroll
    for (int r = 0; r < 4; r++)
        tile[ty + r*8][tx] = W[(size_t)(k0 + ty + r*8) * FOUT + n0 + tx];
    __syncthreads();
    #pragma unroll
    for (int r = 0; r < 4; r++) {
        float v = tile[tx][ty + r*8];   // W[k0+tx][n0+ty+r*8]
        __nv_bfloat16 hi = __float2bfloat16_rn(v);
        __nv_bfloat16 lo = __float2bfloat16_rn(v - __bfloat162float(hi));
        size_t o = (size_t)(n0 + ty + r*8) * FIN + k0 + tx;
        g_wth[o] = hi; g_wtl[o] = lo;
    }
}

// ================= K3: masked LeakyReLU + row softmax =================
#define RPB 8
__global__ __launch_bounds__(256) void softmax_rows(const int* __restrict__ adj,
                                                    float* __restrict__ scores) {
    const int row0 = blockIdx.x * RPB;    // global row in [0, BB*NN)
    const int b = row0 >> 12;
    __shared__ float s_an[NN];            // 16 KB
    __shared__ float red[16];
    const int tid = threadIdx.x;
    const int warp = tid >> 5, lane = tid & 31;

    const float4* anb = (const float4*)(g_an + (size_t)b * NN);
    float4* s_an4 = (float4*)s_an;
    for (int j = tid; j < NN / 4; j += 256) s_an4[j] = anb[j];
    __syncthreads();

    for (int rp = 0; rp < RPB; rp += 2) {
        const int rowA = row0 + rp;
        const int rowB = rowA + 1;
        const float asvA = g_as[rowA];
        const float asvB = g_as[rowB];
        const int4* aA4 = (const int4*)(adj + (size_t)rowA * NN);
        const int4* aB4 = (const int4*)(adj + (size_t)rowB * NN);

        float eA[16], eB[16];
        float mA = -3.0e38f, mB = -3.0e38f;
        #pragma unroll
        for (int g = 0; g < 4; g++) {
            int j4 = tid + g * 256;
            int4 a0 = aA4[j4];
            int4 a1 = aB4[j4];
            float4 an = s_an4[j4];
            float t;
            t = asvA + an.x; t = (t >= 0.f) ? t : 0.2f * t; if (a0.x <= 0) t = NEG_BIG; eA[g*4+0] = t; mA = fmaxf(mA, t);
            t = asvA + an.y; t = (t >= 0.f) ? t : 0.2f * t; if (a0.y <= 0) t = NEG_BIG; eA[g*4+1] = t; mA = fmaxf(mA, t);
            t = asvA + an.z; t = (t >= 0.f) ? t : 0.2f * t; if (a0.z <= 0) t = NEG_BIG; eA[g*4+2] = t; mA = fmaxf(mA, t);
            t = asvA + an.w; t = (t >= 0.f) ? t : 0.2f * t; if (a0.w <= 0) t = NEG_BIG; eA[g*4+3] = t; mA = fmaxf(mA, t);
            t = asvB + an.x; t = (t >= 0.f) ? t : 0.2f * t; if (a1.x <= 0) t = NEG_BIG; eB[g*4+0] = t; mB = fmaxf(mB, t);
            t = asvB + an.y; t = (t >= 0.f) ? t : 0.2f * t; if (a1.y <= 0) t = NEG_BIG; eB[g*4+1] = t; mB = fmaxf(mB, t);
            t = asvB + an.z; t = (t >= 0.f) ? t : 0.2f * t; if (a1.z <= 0) t = NEG_BIG; eB[g*4+2] = t; mB = fmaxf(mB, t);
            t = asvB + an.w; t = (t >= 0.f) ? t : 0.2f * t; if (a1.w <= 0) t = NEG_BIG; eB[g*4+3] = t; mB = fmaxf(mB, t);
        }
        #pragma unroll
        for (int off = 16; off; off >>= 1) {
            mA = fmaxf(mA, __shfl_xor_sync(0xFFFFFFFFu, mA, off));
            mB = fmaxf(mB, __shfl_xor_sync(0xFFFFFFFFu, mB, off));
        }
        if (lane == 0) { red[warp] = mA; red[warp + 8] = mB; }
        __syncthreads();
        float MA = red[0], MB = red[8];
        #pragma unroll
        for (int w = 1; w < 8; w++) {
            MA = fmaxf(MA, red[w]);
            MB = fmaxf(MB, red[w + 8]);
        }
        __syncthreads();

        float sA = 0.f, sB = 0.f;
        #pragma unroll
        for (int i = 0; i < 16; i++) {
            float pA = __expf(eA[i] - MA);   // masked lanes underflow to exact 0
            float pB = __expf(eB[i] - MB);
            eA[i] = pA; eB[i] = pB;
            sA += pA; sB += pB;
        }
        #pragma unroll
        for (int off = 16; off; off >>= 1) {
            sA += __shfl_xor_sync(0xFFFFFFFFu, sA, off);
            sB += __shfl_xor_sync(0xFFFFFFFFu, sB, off);
        }
        if (lane == 0) { red[warp] = sA; red[warp + 8] = sB; }
        __syncthreads();
        float SA = red[0], SB = red[8];
        #pragma unroll
        for (int w = 1; w < 8; w++) {
            SA += red[w];
            SB += red[w + 8];
        }
        const float SinvA = 1.0f / SA;
        const float SinvB = 1.0f / SB;

        float4* pA4 = (float4*)(scores + (size_t)rowA * NN);
        float4* pB4 = (float4*)(scores + (size_t)rowB * NN);
        #pragma unroll
        for (int g = 0; g < 4; g++) {
            int j4 = tid + g * 256;
            pA4[j4] = make_float4(eA[g*4+0] * SinvA, eA[g*4+1] * SinvA,
                                  eA[g*4+2] * SinvA, eA[g*4+3] * SinvA);
            pB4[j4] = make_float4(eB[g*4+0] * SinvB, eB[g*4+1] * SinvB,
                                  eB[g*4+2] * SinvB, eB[g*4+3] * SinvB);
        }
        __syncthreads();   // red reused next pair
    }
}

// ================= launch =================
extern "C" void kernel_launch(void* const* d_in, const int* in_sizes, int n_in,
                              void* d_out, int out_size) {
    const float* x   = (const float*)d_in[0];   // [B,N,Fin]
    const int*   adj = (const int*)  d_in[1];   // [B,N,N]
    const float* W   = (const float*)d_in[2];   // [Fin,Fout]
    const float* a1  = (const float*)d_in[3];   // [Fout,1]
    const float* a2  = (const float*)d_in[4];   // [Fout,1]

    float* out    = (float*)d_out;                       // [B,N,Fout]
    float* scores = out + (size_t)BB * NN * FOUT;        // [B,N,N]

    void *wth, *wtl, *hth;
    cudaGetSymbolAddress(&wth, g_wth);
    cudaGetSymbolAddress(&wtl, g_wtl);
    cudaGetSymbolAddress(&hth, g_hth);

    const int dynsmem = 2 * STAGE + 1024;   // 197632
    cudaFuncSetAttribute(mma_gemm<1>, cudaFuncAttributeMaxDynamicSharedMemorySize, dynsmem);
    cudaFuncSetAttribute(mma_gemm<2>, cudaFuncAttributeMaxDynamicSharedMemorySize, dynsmem);

    // K0: W^T hi/lo + zero attn accumulators (fused)
    wsplit<<<dim3(FIN / 32, FOUT / 32), dim3(32, 8)>>>(W);
    // K1: h = x @ W (bf16 3-term) -> fused h^T fp16 + attn dots
    mma_gemm<2><<<dim3((BB * NN) / 128, 1), NT, dynsmem>>>(
        x, wth, wtl, nullptr, FIN, 0, 0, 0, a1, a2);
    // K3: masked softmax -> scores (second output)
    softmax_rows<<<(BB * NN) / RPB, 256>>>(adj, scores);
    // K4: h_prime = P @ h (fp16 1-term, K-chunk 128), ELU -> out
    mma_gemm<1><<<dim3(NN / 128, BB), NT, dynsmem>>>(
        scores, hth, nullptr, out, NN,
        (size_t)NN * NN, (size_t)FOUT * NN, (size_t)NN * FOUT, nullptr, nullptr);
}

// round 17
// speedup vs baseline: 1.8096x; 1.0394x over previous
#include <cuda_runtime.h>
#include <cuda_bf16.h>
#include <cuda_fp16.h>
#include <cstdint>
#include <math.h>

#define BB   4
#define NN   4096
#define FIN  512
#define FOUT 256
#define NEG_BIG (-9.0e15f)

// ---------------- scratch (no allocations allowed) ----------------
__device__ float g_as[BB * NN];                   // attn_self   (atomic-accumulated)
__device__ float g_an[BB * NN];                   // attn_neigh
__device__ __half g_hth[BB * FOUT * NN];          // h^T (fp16)  [B,256,4096]
__device__ __half g_ph [(size_t)BB * NN * NN];    // P (fp16)    [B,N,N]
__device__ __nv_bfloat16 g_wth[FOUT * FIN];       // W^T hi (bf16)  [256,512]
__device__ __nv_bfloat16 g_wtl[FOUT * FIN];       // W^T lo (bf16)

// ================= helpers =================
__device__ __forceinline__ uint32_t smem_u32(const void* p) {
    uint32_t a;
    asm("{ .reg .u64 t; cvta.to.shared.u64 t, %1; cvt.u32.u64 %0, t; }" : "=r"(a) : "l"(p));
    return a;
}
#define SW128(o) ((o) ^ (((o) >> 3) & 0x70))

__device__ __forceinline__ void cp16(uint32_t dst, const void* src) {
    asm volatile("cp.async.cg.shared.global [%0], [%1], 16;\n" :: "r"(dst), "l"(src));
}
__device__ __forceinline__ void ldsm_x4(uint32_t* r, uint32_t addr) {
    asm volatile("ldmatrix.sync.aligned.m8n8.x4.shared.b16 {%0,%1,%2,%3}, [%4];"
        : "=r"(r[0]), "=r"(r[1]), "=r"(r[2]), "=r"(r[3]) : "r"(addr));
}
__device__ __forceinline__ void mma_bf16(float* d, const uint32_t* a, const uint32_t* b) {
    asm volatile("mma.sync.aligned.m16n8k16.row.col.f32.bf16.bf16.f32 "
        "{%0,%1,%2,%3}, {%4,%5,%6,%7}, {%8,%9}, {%0,%1,%2,%3};"
        : "+f"(d[0]), "+f"(d[1]), "+f"(d[2]), "+f"(d[3])
        : "r"(a[0]), "r"(a[1]), "r"(a[2]), "r"(a[3]), "r"(b[0]), "r"(b[1]));
}
__device__ __forceinline__ void mma_f16(float* d, const uint32_t* a, const uint32_t* b) {
    asm volatile("mma.sync.aligned.m16n8k16.row.col.f32.f16.f16.f32 "
        "{%0,%1,%2,%3}, {%4,%5,%6,%7}, {%8,%9}, {%0,%1,%2,%3};"
        : "+f"(d[0]), "+f"(d[1]), "+f"(d[2]), "+f"(d[3])
        : "r"(a[0]), "r"(a[1]), "r"(a[2]), "r"(a[3]), "r"(b[0]), "r"(b[1]));
}
#define STS64(addr, v0, v1) \
    asm volatile("st.shared.v2.b32 [%0], {%1,%2};" :: "r"(addr), "r"(v0), "r"(v1) : "memory")

// packed hi/lo bf16 split of two floats: hp = bf16x2{lo=x, hi=y}, lp = residuals
__device__ __forceinline__ void split2(float x, float y, uint32_t& hp, uint32_t& lp) {
    asm("cvt.rn.bf16x2.f32 %0, %1, %2;" : "=r"(hp) : "f"(y), "f"(x));
    float lx = x - __uint_as_float(hp << 16);
    float ly = y - __uint_as_float(hp & 0xFFFF0000u);
    asm("cvt.rn.bf16x2.f32 %0, %1, %2;" : "=r"(lp) : "f"(ly), "f"(lx));
}
__device__ __forceinline__ uint32_t packh2(float x, float y) {
    uint32_t h;
    asm("cvt.rn.f16x2.f32 %0, %1, %2;" : "=r"(h) : "f"(y), "f"(x));
    return h;
}

// ================= generalized mma.sync GEMM =================
// C[b][M,256] = A[b][M,Kdim] @ B[b][256,Kdim]^T
// CTA tile 128(M) x 256(N), 512 threads, 16 warps 4(M)x4(N), warp tile 32x64.
// 2 smem stages x 96KB.
// MODE 1 (K4): A = P fp16 (pre-split by softmax) via cp.async; B = h^T fp16;
//              1 MMA term; K chunk 128 (two 64-wide sub-tiles); pure async
//              mainloop; ELU epilogue -> Cg.
// MODE 2 (K1): A = f32 x -> bf16 hi/lo in-kernel; B = W^T bf16 hi/lo;
//              3 MMA terms; K chunk 64; epilogue: h^T fp16 + attn dots.
#define STAGE 98304
#define SMP 261   // smem transpose row pitch (floats)
#define NT  512

template<int MODE>
__global__ __launch_bounds__(NT, 1) void mma_gemm(
    const void* __restrict__ Abase, const void* __restrict__ Bh_,
    const void* __restrict__ Bl_, float* __restrict__ Cbase,
    int Kdim, size_t sA, size_t sB, size_t sC,
    const float* __restrict__ att1, const float* __restrict__ att2)
{
    constexpr int KCH = (MODE == 1) ? 128 : 64;
    constexpr int NKS = KCH / 16;                 // k-steps per chunk (8 / 4)
    // MODE1 layout: A fp16 2x16KB subtiles @0; B fp16 2x32KB subtiles @32768
    // MODE2 layout: A bf16 hi @0, lo @16384; B bf16 hi @32768, lo @65536
    constexpr uint32_t OAL_ = 16384, OBH_ = 32768, OBL_ = 65536;

    extern __shared__ char dynsmem[];
    const int tid = threadIdx.x;
    const int wid = tid >> 5, lane = tid & 31;
    const int mtile = blockIdx.x, b = blockIdx.y;
    const int rowBase = mtile * 128;
    const int wm = wid >> 2, wn = wid & 3;   // warp tile 32(M) x 64(N)

    uint32_t raw = smem_u32(dynsmem);
    uint32_t sbase = (raw + 1023u) & ~1023u;
    char* dbase = dynsmem + (sbase - raw);

    const float* Agf = (const float*)Abase + (size_t)((MODE == 2) ? 1 : 0) *
                       ((size_t)b * sA + (size_t)rowBase * Kdim);
    const char*  Agh = (const char*)Abase + ((size_t)b * sA + (size_t)rowBase * Kdim) * 2;
    const char* Bhg = (const char*)Bh_ + (size_t)b * sB * 2;
    const char* Blg = (const char*)Bl_ + (size_t)b * sB * 2;
    float* Cg = Cbase + (size_t)b * sC;

    // ldmatrix address components (fixed per thread)
    const uint32_t a_row_l = lane & 15;
    const uint32_t a_k16   = (lane >> 4) * 16;
    const uint32_t a_xor   = (a_row_l & 7) << 4;
    uint32_t a_rowoff[2];
    #pragma unroll
    for (int mf = 0; mf < 2; mf++)
        a_rowoff[mf] = (uint32_t)(wm * 32 + mf * 16 + a_row_l) * 128;

    const uint32_t b_nl  = (lane & 7) + ((lane >> 4) & 1) * 8;
    const uint32_t b_k16 = ((lane >> 3) & 1) * 16;
    const uint32_t b_xor = (b_nl & 7) << 4;
    uint32_t b_rowoff[4];
    #pragma unroll
    for (int np = 0; np < 4; np++)
        b_rowoff[np] = (uint32_t)(wn * 64 + np * 16 + b_nl) * 128;

    float acc[2][8][4] = {};
    float4 av[4];

    // ---- stage-fill lambdas ----
    auto cpA = [&](uint32_t stb, int kc) {        // MODE1: A fp16 via cp.async
        #pragma unroll
        for (int l = 0; l < 4; l++) {             // 128 rows x 16 chunks of 16B
            int id = tid + l * NT;
            int r = id >> 4, ch = id & 15;
            size_t so = ((size_t)r * Kdim + kc + ch * 8) * 2;   // bytes
            uint32_t sub = (uint32_t)(ch >> 3);
            uint32_t sw = SW128((uint32_t)(r * 128 + (ch & 7) * 16));
            cp16(stb + sub * 16384 + sw, Agh + so);
        }
    };
    auto ldA = [&](int kc) {                      // MODE2: f32 loads
        #pragma unroll
        for (int l = 0; l < 4; l++) {
            int id = tid + l * NT;
            int r = id >> 4, ch = id & 15;
            av[l] = *(const float4*)(Agf + (size_t)r * Kdim + kc + ch * 4);
        }
    };
    auto stA = [&](uint32_t stb) {                // MODE2: bf16 hi/lo STS
        #pragma unroll
        for (int l = 0; l < 4; l++) {
            int id = tid + l * NT;
            int r = id >> 4, ch = id & 15;
            float4 v = av[l];
            uint32_t h01, l01, h23, l23;
            split2(v.x, v.y, h01, l01);
            split2(v.z, v.w, h23, l23);
            uint32_t sw = SW128((uint32_t)(r * 128 + ch * 8));
            STS64(stb + sw, h01, h23);
            STS64(stb + OAL_ + sw, l01, l23);
        }
    };
    auto cpB = [&](uint32_t stb, int kc) {
        if (MODE == 1) {
            // B fp16: 256 rows x 128 k = 4096 x 16B, 8 per thread
            #pragma unroll
            for (int l = 0; l < 8; l++) {
                int id = tid + l * NT;
                int r = id >> 4, ch = id & 15;
                size_t so = ((size_t)r * Kdim + kc + ch * 8) * 2;   // bytes
                uint32_t sub = (uint32_t)(ch >> 3);
                uint32_t sw = SW128((uint32_t)(r * 128 + (ch & 7) * 16));
                cp16(stb + OBH_ + sub * 32768 + sw, Bhg + so);
            }
        } else {
            #pragma unroll
            for (int l = 0; l < 4; l++) {
                int id = tid + l * NT;
                int r = id >> 3, ch = id & 7;
                size_t so = ((size_t)r * Kdim + kc + ch * 8) * 2;   // bytes
                uint32_t sw = SW128((uint32_t)(r * 128 + ch * 16));
                cp16(stb + OBH_ + sw, Bhg + so);
                cp16(stb + OBL_ + sw, Blg + so);
            }
        }
    };
    auto compute = [&](uint32_t stb, int ks0, int ks1) {
        #pragma unroll
        for (int ks = ks0; ks < ks1; ks++) {
            if (MODE == 1) {
                uint32_t kk = (uint32_t)(ks >> 2), k4 = (uint32_t)(ks & 3);
                uint32_t akt = kk * 16384 + ((k4 * 32 + a_k16) ^ a_xor);
                uint32_t bkt = OBH_ + kk * 32768 + ((k4 * 32 + b_k16) ^ b_xor);
                uint32_t ah[2][4];
                #pragma unroll
                for (int mf = 0; mf < 2; mf++)
                    ldsm_x4(ah[mf], stb + a_rowoff[mf] + akt);
                #pragma unroll
                for (int np = 0; np < 4; np++) {
                    uint32_t bh[4];
                    ldsm_x4(bh, stb + bkt + b_rowoff[np]);
                    #pragma unroll
                    for (int mf = 0; mf < 2; mf++) mma_f16(acc[mf][np*2],   ah[mf], &bh[0]);
                    #pragma unroll
                    for (int mf = 0; mf < 2; mf++) mma_f16(acc[mf][np*2+1], ah[mf], &bh[2]);
                }
            } else {
                uint32_t akt = ((uint32_t)(ks * 32) + a_k16) ^ a_xor;
                uint32_t bkt = ((uint32_t)(ks * 32) + b_k16) ^ b_xor;
                uint32_t ah[2][4], al[2][4];
                #pragma unroll
                for (int mf = 0; mf < 2; mf++) {
                    ldsm_x4(ah[mf], stb + a_rowoff[mf] + akt);
                    ldsm_x4(al[mf], stb + OAL_ + a_rowoff[mf] + akt);
                }
                #pragma unroll
                for (int np = 0; np < 4; np++) {
                    uint32_t bh[4], bl[4];
                    ldsm_x4(bh, stb + OBH_ + b_rowoff[np] + bkt);
                    ldsm_x4(bl, stb + OBL_ + b_rowoff[np] + bkt);
                    // per-accumulator term order ah*bh -> ah*bl -> al*bh
                    #pragma unroll
                    for (int mf = 0; mf < 2; mf++) mma_bf16(acc[mf][np*2],   ah[mf], &bh[0]);
                    #pragma unroll
                    for (int mf = 0; mf < 2; mf++) mma_bf16(acc[mf][np*2+1], ah[mf], &bh[2]);
                    #pragma unroll
                    for (int mf = 0; mf < 2; mf++) mma_bf16(acc[mf][np*2],   ah[mf], &bl[0]);
                    #pragma unroll
                    for (int mf = 0; mf < 2; mf++) mma_bf16(acc[mf][np*2+1], ah[mf], &bl[2]);
                    #pragma unroll
                    for (int mf = 0; mf < 2; mf++) mma_bf16(acc[mf][np*2],   al[mf], &bh[0]);
                    #pragma unroll
                    for (int mf = 0; mf < 2; mf++) mma_bf16(acc[mf][np*2+1], al[mf], &bh[2]);
                }
            }
        }
    };

    // ---- pipeline ----
    const int nch = Kdim / KCH;
    int buf = 0;
    if (MODE == 1) {
        cpA(sbase, 0);
        cpB(sbase, 0);
        asm volatile("cp.async.commit_group;" ::: "memory");
        asm volatile("cp.async.wait_group 0;" ::: "memory");
        __syncthreads();
        for (int c = 0; c < nch; c++) {
            int nb = buf ^ 1;
            bool more = (c + 1 < nch);
            if (more) {
                cpA(sbase + nb * STAGE, (c + 1) * KCH);
                cpB(sbase + nb * STAGE, (c + 1) * KCH);
                asm volatile("cp.async.commit_group;" ::: "memory");
            }
            compute(sbase + buf * STAGE, 0, NKS);
            if (more) {
                asm volatile("cp.async.wait_group 0;" ::: "memory");
                __syncthreads();
            }
            buf = nb;
        }
    } else {
        ldA(0);
        cpB(sbase, 0);
        asm volatile("cp.async.commit_group;" ::: "memory");
        stA(sbase);
        asm volatile("cp.async.wait_group 0;" ::: "memory");
        __syncthreads();
        for (int c = 0; c < nch; c++) {
            int nb = buf ^ 1;
            bool more = (c + 1 < nch);
            if (more) {
                ldA((c + 1) * KCH);
                cpB(sbase + nb * STAGE, (c + 1) * KCH);
                asm volatile("cp.async.commit_group;" ::: "memory");
            }
            compute(sbase + buf * STAGE, 0, NKS / 2);
            if (more) stA(sbase + nb * STAGE);      // overlaps 2nd compute half
            compute(sbase + buf * STAGE, NKS / 2, NKS);
            if (more) {
                asm volatile("cp.async.wait_group 0;" ::: "memory");
                __syncthreads();
            }
            buf = nb;
        }
    }

    if (MODE == 1) {
        // ---- ELU + store ----
        #pragma unroll
        for (int mf = 0; mf < 2; mf++) {
            int r0 = rowBase + wm * 32 + mf * 16 + (lane >> 2);
            float* p0 = Cg + (size_t)r0 * FOUT + wn * 64 + (lane & 3) * 2;
            #pragma unroll
            for (int nf = 0; nf < 8; nf++) {
                float* q = p0 + nf * 8;
                float v0 = acc[mf][nf][0], v1 = acc[mf][nf][1];
                float v2 = acc[mf][nf][2], v3 = acc[mf][nf][3];
                v0 = (v0 > 0.f) ? v0 : expm1f(v0);
                v1 = (v1 > 0.f) ? v1 : expm1f(v1);
                v2 = (v2 > 0.f) ? v2 : expm1f(v2);
                v3 = (v3 > 0.f) ? v3 : expm1f(v3);
                *(float2*)q = make_float2(v0, v1);
                *(float2*)(q + 8 * FOUT) = make_float2(v2, v3);
            }
        }
    } else {
        // ---- attn dot partials from fragments ----
        float a1v[16], a2v[16];
        #pragma unroll
        for (int nf = 0; nf < 8; nf++) {
            int c0 = wn * 64 + nf * 8 + (lane & 3) * 2;
            a1v[nf*2+0] = __ldg(att1 + c0);  a1v[nf*2+1] = __ldg(att1 + c0 + 1);
            a2v[nf*2+0] = __ldg(att2 + c0);  a2v[nf*2+1] = __ldg(att2 + c0 + 1);
        }
        #pragma unroll
        for (int mf = 0; mf < 2; mf++) {
            float s1a = 0.f, s2a = 0.f, s1b = 0.f, s2b = 0.f;
            #pragma unroll
            for (int nf = 0; nf < 8; nf++) {
                s1a += acc[mf][nf][0] * a1v[nf*2] + acc[mf][nf][1] * a1v[nf*2+1];
                s2a += acc[mf][nf][0] * a2v[nf*2] + acc[mf][nf][1] * a2v[nf*2+1];
                s1b += acc[mf][nf][2] * a1v[nf*2] + acc[mf][nf][3] * a1v[nf*2+1];
                s2b += acc[mf][nf][2] * a2v[nf*2] + acc[mf][nf][3] * a2v[nf*2+1];
            }
            #pragma unroll
            for (int off = 1; off <= 2; off <<= 1) {
                s1a += __shfl_xor_sync(0xFFFFFFFFu, s1a, off);
                s2a += __shfl_xor_sync(0xFFFFFFFFu, s2a, off);
                s1b += __shfl_xor_sync(0xFFFFFFFFu, s1b, off);
                s2b += __shfl_xor_sync(0xFFFFFFFFu, s2b, off);
            }
            if ((lane & 3) == 0) {
                int rA = rowBase + wm * 32 + mf * 16 + (lane >> 2);
                atomicAdd(&g_as[rA],     s1a);  atomicAdd(&g_an[rA],     s2a);
                atomicAdd(&g_as[rA + 8], s1b);  atomicAdd(&g_an[rA + 8], s2b);
            }
        }
        // ---- transpose via smem, single fp16, coalesced store ----
        float* sm = (float*)dbase;                 // [128][SMP] f32 = 130.5 KB
        __syncthreads();                           // mainloop smem reads done
        #pragma unroll
        for (int mf = 0; mf < 2; mf++) {
            int r = wm * 32 + mf * 16 + (lane >> 2);
            int c = wn * 64 + (lane & 3) * 2;
            #pragma unroll
            for (int nf = 0; nf < 8; nf++) {
                sm[r * SMP + c + nf*8]           = acc[mf][nf][0];
                sm[r * SMP + c + nf*8 + 1]       = acc[mf][nf][1];
                sm[(r + 8) * SMP + c + nf*8]     = acc[mf][nf][2];
                sm[(r + 8) * SMP + c + nf*8 + 1] = acc[mf][nf][3];
            }
        }
        __syncthreads();
        const int bb = rowBase >> 12;
        const int mbase = rowBase & (NN - 1);
        uint32_t* dh = (uint32_t*)(g_hth + (size_t)bb * FOUT * NN);
        for (int idx = tid; idx < FOUT * 64; idx += NT) {
            int n = idx >> 6, mp = idx & 63;
            float v0 = sm[(2*mp)     * SMP + n];
            float v1 = sm[(2*mp + 1) * SMP + n];
            size_t o = (((size_t)n * NN + mbase) >> 1) + mp;
            dh[o] = packh2(v0, v1);
        }
    }
}

// ================= K0: W^T hi/lo bf16 split + zero attn accumulators =======
__global__ __launch_bounds__(256) void wsplit(const float* __restrict__ W) {
    __shared__ float tile[32][33];
    const int k0 = blockIdx.x * 32, n0 = blockIdx.y * 32;
    const int tx = threadIdx.x, ty = threadIdx.y;
    const int tid = ty * 32 + tx;
    {
        int bid = blockIdx.y * 16 + blockIdx.x;
        if (tid < 128) {
            int i = bid * 128 + tid;
            g_as[i] = 0.f;
            g_an[i] = 0.f;
        }
    }
    #pragma unroll
    for (int r = 0; r < 4; r++)
        tile[ty + r*8][tx] = W[(size_t)(k0 + ty + r*8) * FOUT + n0 + tx];
    __syncthreads();
    #pragma unroll
    for (int r = 0; r < 4; r++) {
        float v = tile[tx][ty + r*8];   // W[k0+tx][n0+ty+r*8]
        __nv_bfloat16 hi = __float2bfloat16_rn(v);
        __nv_bfloat16 lo = __float2bfloat16_rn(v - __bfloat162float(hi));
        size_t o = (size_t)(n0 + ty + r*8) * FIN + k0 + tx;
        g_wth[o] = hi; g_wtl[o] = lo;
    }
}

// ================= K3: masked LeakyReLU + row softmax (+ fp16 P) ===========
#define RPB 8
__global__ __launch_bounds__(256) void softmax_rows(const int* __restrict__ adj,
                                                    float* __restrict__ scores) {
    const int row0 = blockIdx.x * RPB;    // global row in [0, BB*NN)
    const int b = row0 >> 12;
    __shared__ float s_an[NN];            // 16 KB
    __shared__ float red[16];
    const int tid = threadIdx.x;
    const int warp = tid >> 5, lane = tid & 31;

    const float4* anb = (const float4*)(g_an + (size_t)b * NN);
    float4* s_an4 = (float4*)s_an;
    for (int j = tid; j < NN / 4; j += 256) s_an4[j] = anb[j];
    __syncthreads();

    for (int rp = 0; rp < RPB; rp += 2) {
        const int rowA = row0 + rp;
        const int rowB = rowA + 1;
        const float asvA = g_as[rowA];
        const float asvB = g_as[rowB];
        const int4* aA4 = (const int4*)(adj + (size_t)rowA * NN);
        const int4* aB4 = (const int4*)(adj + (size_t)rowB * NN);

        float eA[16], eB[16];
        float mA = -3.0e38f, mB = -3.0e38f;
        #pragma unroll
        for (int g = 0; g < 4; g++) {
            int j4 = tid + g * 256;
            int4 a0 = aA4[j4];
            int4 a1 = aB4[j4];
            float4 an = s_an4[j4];
            float t;
            t = asvA + an.x; t = (t >= 0.f) ? t : 0.2f * t; if (a0.x <= 0) t = NEG_BIG; eA[g*4+0] = t; mA = fmaxf(mA, t);
            t = asvA + an.y; t = (t >= 0.f) ? t : 0.2f * t; if (a0.y <= 0) t = NEG_BIG; eA[g*4+1] = t; mA = fmaxf(mA, t);
            t = asvA + an.z; t = (t >= 0.f) ? t : 0.2f * t; if (a0.z <= 0) t = NEG_BIG; eA[g*4+2] = t; mA = fmaxf(mA, t);
            t = asvA + an.w; t = (t >= 0.f) ? t : 0.2f * t; if (a0.w <= 0) t = NEG_BIG; eA[g*4+3] = t; mA = fmaxf(mA, t);
            t = asvB + an.x; t = (t >= 0.f) ? t : 0.2f * t; if (a1.x <= 0) t = NEG_BIG; eB[g*4+0] = t; mB = fmaxf(mB, t);
            t = asvB + an.y; t = (t >= 0.f) ? t : 0.2f * t; if (a1.y <= 0) t = NEG_BIG; eB[g*4+1] = t; mB = fmaxf(mB, t);
            t = asvB + an.z; t = (t >= 0.f) ? t : 0.2f * t; if (a1.z <= 0) t = NEG_BIG; eB[g*4+2] = t; mB = fmaxf(mB, t);
            t = asvB + an.w; t = (t >= 0.f) ? t : 0.2f * t; if (a1.w <= 0) t = NEG_BIG; eB[g*4+3] = t; mB = fmaxf(mB, t);
        }
        #pragma unroll
        for (int off = 16; off; off >>= 1) {
            mA = fmaxf(mA, __shfl_xor_sync(0xFFFFFFFFu, mA, off));
            mB = fmaxf(mB, __shfl_xor_sync(0xFFFFFFFFu, mB, off));
        }
        if (lane == 0) { red[warp] = mA; red[warp + 8] = mB; }
        __syncthreads();
        float MA = red[0], MB = red[8];
        #pragma unroll
        for (int w = 1; w < 8; w++) {
            MA = fmaxf(MA, red[w]);
            MB = fmaxf(MB, red[w + 8]);
        }
        __syncthreads();

        float sA = 0.f, sB = 0.f;
        #pragma unroll
        for (int i = 0; i < 16; i++) {
            float pA = __expf(eA[i] - MA);   // masked lanes underflow to exact 0
            float pB = __expf(eB[i] - MB);
            eA[i] = pA; eB[i] = pB;
            sA += pA; sB += pB;
        }
        #pragma unroll
        for (int off = 16; off; off >>= 1) {
            sA += __shfl_xor_sync(0xFFFFFFFFu, sA, off);
            sB += __shfl_xor_sync(0xFFFFFFFFu, sB, off);
        }
        if (lane == 0) { red[warp] = sA; red[warp + 8] = sB; }
        __syncthreads();
        float SA = red[0], SB = red[8];
        #pragma unroll
        for (int w = 1; w < 8; w++) {
            SA += red[w];
            SB += red[w + 8];
        }
        const float SinvA = 1.0f / SA;
        const float SinvB = 1.0f / SB;

        float4* pA4 = (float4*)(scores + (size_t)rowA * NN);
        float4* pB4 = (float4*)(scores + (size_t)rowB * NN);
        uint2* phA = (uint2*)(g_ph + (size_t)rowA * NN);
        uint2* phB = (uint2*)(g_ph + (size_t)rowB * NN);
        #pragma unroll
        for (int g = 0; g < 4; g++) {
            int j4 = tid + g * 256;
            float4 vA = make_float4(eA[g*4+0] * SinvA, eA[g*4+1] * SinvA,
                                    eA[g*4+2] * SinvA, eA[g*4+3] * SinvA);
            float4 vB = make_float4(eB[g*4+0] * SinvB, eB[g*4+1] * SinvB,
                                    eB[g*4+2] * SinvB, eB[g*4+3] * SinvB);
            pA4[j4] = vA;
            pB4[j4] = vB;
            phA[j4] = make_uint2(packh2(vA.x, vA.y), packh2(vA.z, vA.w));
            phB[j4] = make_uint2(packh2(vB.x, vB.y), packh2(vB.z, vB.w));
        }
        __syncthreads();   // red reused next pair
    }
}

// ================= launch =================
extern "C" void kernel_launch(void* const* d_in, const int* in_sizes, int n_in,
                              void* d_out, int out_size) {
    const float* x   = (const float*)d_in[0];   // [B,N,Fin]
    const int*   adj = (const int*)  d_in[1];   // [B,N,N]
    const float* W   = (const float*)d_in[2];   // [Fin,Fout]
    const float* a1  = (const float*)d_in[3];   // [Fout,1]
    const float* a2  = (const float*)d_in[4];   // [Fout,1]

    float* out    = (float*)d_out;                       // [B,N,Fout]
    float* scores = out + (size_t)BB * NN * FOUT;        // [B,N,N]

    void *wth, *wtl, *hth, *ph;
    cudaGetSymbolAddress(&wth, g_wth);
    cudaGetSymbolAddress(&wtl, g_wtl);
    cudaGetSymbolAddress(&hth, g_hth);
    cudaGetSymbolAddress(&ph,  g_ph);

    const int dynsmem = 2 * STAGE + 1024;   // 197632
    cudaFuncSetAttribute(mma_gemm<1>, cudaFuncAttributeMaxDynamicSharedMemorySize, dynsmem);
    cudaFuncSetAttribute(mma_gemm<2>, cudaFuncAttributeMaxDynamicSharedMemorySize, dynsmem);

    // K0: W^T hi/lo + zero attn accumulators (fused)
    wsplit<<<dim3(FIN / 32, FOUT / 32), dim3(32, 8)>>>(W);
    // K1: h = x @ W (bf16 3-term) -> fused h^T fp16 + attn dots
    mma_gemm<2><<<dim3((BB * NN) / 128, 1), NT, dynsmem>>>(
        x, wth, wtl, nullptr, FIN, 0, 0, 0, a1, a2);
    // K3: masked softmax -> scores f32 (second output) + P fp16
    softmax_rows<<<(BB * NN) / RPB, 256>>>(adj, scores);
    // K4: h_prime = P @ h (fp16 1-term, pure async, K-chunk 128), ELU -> out
    mma_gemm<1><<<dim3(NN / 128, BB), NT, dynsmem>>>(
        ph, hth, nullptr, out, NN,
        (size_t)NN * NN, (size_t)FOUT * NN, (size_t)NN * FOUT, nullptr, nullptr);
}